// round 1
// baseline (speedup 1.0000x reference)
#include <cuda_runtime.h>
#include <math.h>

#define CHI 64
#define CHO 64
#define HH 128
#define WW 128
#define BB 4
#define HW (HH*WW)          /* 16384 */
#define NPIX (BB*HW)        /* 65536 */

// Scratch (static device globals: allocation-free per harness rules)
__device__ float g_off[BB*27*HW];     // offset-conv output (27 ch)
__device__ float g_y[BB*CHO*HW];      // pre-BN deform-conv output
__device__ float g_scale[CHO];
__device__ float g_shift[CHO];

// ---------------------------------------------------------------------------
// Kernel A: offset conv, 64 -> 27 channels, 3x3, pad 1.
// One thread per pixel, all 27 output channels in registers.
// Weights staged in SMEM as [kpos][cin][28] (padded to 28 for float4 loads).
// ---------------------------------------------------------------------------
__global__ __launch_bounds__(256, 1)
void offset_conv_kernel(const float* __restrict__ x,
                        const float* __restrict__ w_off,
                        const float* __restrict__ b_off) {
    extern __shared__ float Wo[];  // 9*64*28 floats = 64512 B
    const int tid = threadIdx.x;
    for (int i = tid; i < 9*64*28; i += blockDim.x) {
        int kk = i / (64*28);
        int r  = i % (64*28);
        int c  = r / 28;
        int oc = r % 28;
        Wo[i] = (oc < 27) ? w_off[oc*(64*9) + c*9 + kk] : 0.f;
    }
    __syncthreads();

    const int p   = blockIdx.x * blockDim.x + tid;
    const int b   = p >> 14;
    const int rem = p & 16383;
    const int h   = rem >> 7;
    const int wx  = rem & 127;

    float acc[28];
    #pragma unroll
    for (int i = 0; i < 28; i++) acc[i] = 0.f;

    const float* xb = x + b * (CHI*HW);
    #pragma unroll
    for (int ky = 0; ky < 3; ky++) {
        const int yy = h + ky - 1;
        if (yy < 0 || yy >= HH) continue;
        #pragma unroll
        for (int kx = 0; kx < 3; kx++) {
            const int xx = wx + kx - 1;
            if (xx < 0 || xx >= WW) continue;
            const float*  xp = xb + yy*WW + xx;
            const float4* wp = (const float4*)(Wo + (ky*3+kx)*(64*28));
            #pragma unroll 4
            for (int c = 0; c < 64; c++) {
                const float xv = xp[c*HW];
                const float4* w4 = wp + c*7;
                #pragma unroll
                for (int j = 0; j < 7; j++) {
                    float4 v = w4[j];
                    acc[4*j+0] += xv * v.x;
                    acc[4*j+1] += xv * v.y;
                    acc[4*j+2] += xv * v.z;
                    acc[4*j+3] += xv * v.w;
                }
            }
        }
    }
    float* ob = g_off + b*(27*HW) + rem;
    #pragma unroll
    for (int oc = 0; oc < 27; oc++)
        ob[oc*HW] = acc[oc] + b_off[oc];
}

// ---------------------------------------------------------------------------
// Kernel B: deformable sampling + 576x64 contraction per pixel.
// One thread per pixel; 64 fp32 accumulators in registers.
// Tap weights fold bilinear * validity * sigmoid(mask) -> 4 LDG + 4 FMA per
// (kk, c), then 64 FMA vs SMEM-broadcast float4 weights [kk][c][o].
// ---------------------------------------------------------------------------
__global__ __launch_bounds__(256, 1)
void deform_kernel(const float* __restrict__ x,
                   const float* __restrict__ w,
                   const float* __restrict__ bias) {
    extern __shared__ float Ws[];  // 9*64*64 floats = 147456 B
    const int tid = threadIdx.x;
    for (int i = tid; i < 9*64*64; i += blockDim.x) {
        int o  = i / 576;
        int r  = i % 576;
        int c  = r / 9;
        int kk = r % 9;
        Ws[kk*4096 + c*64 + o] = w[i];
    }
    __syncthreads();

    const int p   = blockIdx.x * blockDim.x + tid;
    const int b   = p >> 14;
    const int rem = p & 16383;
    const int h   = rem >> 7;
    const int wx  = rem & 127;

    float acc[64];
    #pragma unroll
    for (int i = 0; i < 64; i++) acc[i] = 0.f;

    const float* xb   = x + b*(CHI*HW);
    const float* offb = g_off + b*(27*HW) + rem;

    for (int kk = 0; kk < 9; kk++) {
        const float dy = offb[(2*kk  )*HW];
        const float dx = offb[(2*kk+1)*HW];
        const float ml = offb[(18+kk)*HW];
        const float mask = 1.f / (1.f + __expf(-ml));
        const int ky = kk / 3, kx = kk % 3;
        const float py = (float)(h  - 1 + ky) + dy;
        const float px = (float)(wx - 1 + kx) + dx;
        const float fy0 = floorf(py);
        const float fx0 = floorf(px);
        const float wy  = py - fy0;
        const float wxf = px - fx0;
        const int iy0 = (int)fy0, ix0 = (int)fx0;
        const int iy1 = iy0 + 1,  ix1 = ix0 + 1;
        const float vy0 = (iy0 >= 0 && iy0 < HH) ? 1.f : 0.f;
        const float vy1 = (iy1 >= 0 && iy1 < HH) ? 1.f : 0.f;
        const float vx0 = (ix0 >= 0 && ix0 < WW) ? 1.f : 0.f;
        const float vx1 = (ix1 >= 0 && ix1 < WW) ? 1.f : 0.f;
        const int cy0 = min(max(iy0,0),HH-1), cy1 = min(max(iy1,0),HH-1);
        const int cx0 = min(max(ix0,0),WW-1), cx1 = min(max(ix1,0),WW-1);
        const float w00 = (1.f-wy)*(1.f-wxf)*vy0*vx0*mask;
        const float w01 = (1.f-wy)*wxf      *vy0*vx1*mask;
        const float w10 = wy      *(1.f-wxf)*vy1*vx0*mask;
        const float w11 = wy      *wxf      *vy1*vx1*mask;
        const int i00 = cy0*WW + cx0;
        const int i01 = cy0*WW + cx1;
        const int i10 = cy1*WW + cx0;
        const int i11 = cy1*WW + cx1;
        const float4* wkk = (const float4*)(Ws + kk*4096);
        #pragma unroll 2
        for (int c = 0; c < 64; c++) {
            const float* xp = xb + c*HW;
            const float v = w00*xp[i00] + w01*xp[i01] + w10*xp[i10] + w11*xp[i11];
            const float4* w4 = wkk + c*16;
            #pragma unroll
            for (int j = 0; j < 16; j++) {
                float4 wv = w4[j];
                acc[4*j+0] += v*wv.x;
                acc[4*j+1] += v*wv.y;
                acc[4*j+2] += v*wv.z;
                acc[4*j+3] += v*wv.w;
            }
        }
    }
    float* yb = g_y + b*(CHO*HW) + rem;
    #pragma unroll
    for (int o = 0; o < 64; o++)
        yb[o*HW] = acc[o] + bias[o];
}

// ---------------------------------------------------------------------------
// Kernel C: deterministic per-channel mean/var -> scale/shift.
// One block per channel; fixed-order tree reduction (no float atomics).
// ---------------------------------------------------------------------------
__global__ __launch_bounds__(256)
void stats_kernel(const float* __restrict__ gamma,
                  const float* __restrict__ beta) {
    const int ch  = blockIdx.x;
    const int tid = threadIdx.x;
    float s = 0.f, ss = 0.f;
    const float* yc = g_y + ch*HW;
    for (int j = tid; j < NPIX; j += blockDim.x) {
        const int b = j >> 14;
        const int q = j & 16383;
        const float v = yc[b*(CHO*HW) + q];
        s += v; ss += v*v;
    }
    __shared__ float sh_s[256], sh_ss[256];
    sh_s[tid] = s; sh_ss[tid] = ss;
    __syncthreads();
    for (int st = 128; st > 0; st >>= 1) {
        if (tid < st) { sh_s[tid] += sh_s[tid+st]; sh_ss[tid] += sh_ss[tid+st]; }
        __syncthreads();
    }
    if (tid == 0) {
        const float inv  = 1.f / (float)NPIX;
        const float mean = sh_s[0] * inv;
        const float var  = sh_ss[0] * inv - mean*mean;
        const float rstd = rsqrtf(var + 1e-5f);
        const float sc   = rstd * gamma[ch];
        g_scale[ch] = sc;
        g_shift[ch] = beta[ch] - mean*sc;
    }
}

// ---------------------------------------------------------------------------
// Kernel D: normalize + ReLU -> d_out
// ---------------------------------------------------------------------------
__global__ __launch_bounds__(256)
void norm_kernel(float* __restrict__ out) {
    const int i = blockIdx.x * blockDim.x + threadIdx.x;
    if (i < BB*CHO*HW) {
        const int c = (i >> 14) & 63;
        const float v = g_y[i]*g_scale[c] + g_shift[c];
        out[i] = v > 0.f ? v : 0.f;
    }
}

extern "C" void kernel_launch(void* const* d_in, const int* in_sizes, int n_in,
                              void* d_out, int out_size) {
    const float* x     = (const float*)d_in[0];
    const float* w_off = (const float*)d_in[1];
    const float* b_off = (const float*)d_in[2];
    const float* w     = (const float*)d_in[3];
    const float* b     = (const float*)d_in[4];
    const float* gamma = (const float*)d_in[5];
    const float* beta  = (const float*)d_in[6];
    float* out = (float*)d_out;

    cudaFuncSetAttribute(offset_conv_kernel,
                         cudaFuncAttributeMaxDynamicSharedMemorySize, 9*64*28*4);
    cudaFuncSetAttribute(deform_kernel,
                         cudaFuncAttributeMaxDynamicSharedMemorySize, 9*64*64*4);

    offset_conv_kernel<<<NPIX/256, 256, 9*64*28*4>>>(x, w_off, b_off);
    deform_kernel<<<NPIX/256, 256, 9*64*64*4>>>(x, w, b);
    stats_kernel<<<64, 256>>>(gamma, beta);
    norm_kernel<<<(BB*CHO*HW + 255)/256, 256>>>(out);
}

// round 4
// speedup vs baseline: 1.0053x; 1.0053x over previous
#include <cuda_runtime.h>
#include <math.h>

#define CHI 64
#define CHO 64
#define HH 128
#define WW 128
#define BB 4
#define HW (HH*WW)          /* 16384 */
#define NPIX (BB*HW)        /* 65536 */

// Scratch (static device globals: allocation-free per harness rules)
__device__ float g_off[BB*27*HW];     // offset-conv output (27 ch)
__device__ float g_y[BB*CHO*HW];      // pre-BN deform-conv output
__device__ float g_part[64*8*2];      // BN stage-1 partials [ch][slice][{sum,sumsq}]
__device__ float g_scale[CHO];
__device__ float g_shift[CHO];

// ---- packed f32x2 helpers (sm_103a FFMA2 path) ------------------------------
__device__ __forceinline__ unsigned long long pack2(float lo, float hi) {
    unsigned long long r;
    asm("mov.b64 %0, {%1, %2};" : "=l"(r) : "f"(lo), "f"(hi));
    return r;
}
__device__ __forceinline__ void unpack2(unsigned long long v, float& lo, float& hi) {
    asm("mov.b64 {%0, %1}, %2;" : "=f"(lo), "=f"(hi) : "l"(v));
}
__device__ __forceinline__ unsigned long long fma2(unsigned long long a,
                                                   unsigned long long b,
                                                   unsigned long long c) {
    unsigned long long d;
    asm("fma.rn.f32x2 %0, %1, %2, %3;" : "=l"(d) : "l"(a), "l"(b), "l"(c));
    return d;
}

// ---------------------------------------------------------------------------
// Kernel A: offset conv, 64 -> 27 channels, 3x3, pad 1.
// One thread per pixel; 28 accumulators as 14 packed f32x2.
// Weights staged in SMEM as [kpos][cin][28] (27 padded to 28), float4 loads.
// ---------------------------------------------------------------------------
__global__ __launch_bounds__(256, 1)
void offset_conv_kernel(const float* __restrict__ x,
                        const float* __restrict__ w_off,
                        const float* __restrict__ b_off) {
    extern __shared__ float Wo[];  // 9*64*28 floats = 64512 B
    const int tid = threadIdx.x;
    for (int i = tid; i < 9*64*28; i += blockDim.x) {
        int kk = i / (64*28);
        int r  = i % (64*28);
        int c  = r / 28;
        int oc = r % 28;
        Wo[i] = (oc < 27) ? w_off[oc*(64*9) + c*9 + kk] : 0.f;
    }
    __syncthreads();

    const int p   = blockIdx.x * blockDim.x + tid;
    const int b   = p >> 14;
    const int rem = p & 16383;
    const int h   = rem >> 7;
    const int wx  = rem & 127;

    unsigned long long acc[14];
    #pragma unroll
    for (int i = 0; i < 14; i++) acc[i] = 0ull;

    const float* xb = x + b * (CHI*HW);
    #pragma unroll
    for (int ky = 0; ky < 3; ky++) {
        const int yy = h + ky - 1;
        if (yy < 0 || yy >= HH) continue;
        #pragma unroll
        for (int kx = 0; kx < 3; kx++) {
            const int xx = wx + kx - 1;
            if (xx < 0 || xx >= WW) continue;
            const float*  xp = xb + yy*WW + xx;
            const float4* wp = (const float4*)(Wo + (ky*3+kx)*(64*28));
            for (int c = 0; c < 64; c++) {
                const float xv = xp[c*HW];
                const unsigned long long vv = pack2(xv, xv);
                const float4* w4 = wp + c*7;   // 7 x 16B = 28 floats
                #pragma unroll
                for (int j = 0; j < 7; j++) {
                    float4 t = w4[j];
                    acc[2*j+0] = fma2(vv, pack2(t.x, t.y), acc[2*j+0]);
                    acc[2*j+1] = fma2(vv, pack2(t.z, t.w), acc[2*j+1]);
                }
            }
        }
    }
    float* ob = g_off + b*(27*HW) + rem;
    #pragma unroll
    for (int j = 0; j < 14; j++) {
        float lo, hi;
        unpack2(acc[j], lo, hi);
        const int oc = 2*j;
        ob[oc*HW] = lo + b_off[oc];
        if (oc + 1 < 27) ob[(oc+1)*HW] = hi + b_off[oc+1];
    }
}

// ---------------------------------------------------------------------------
// Kernel B: deformable sampling + 576x64 contraction per pixel.
// One thread per pixel; 64 accumulators as 32 packed f32x2.
// Tap weights fold bilinear*validity*sigmoid(mask); 4 LDG + 4 FMA per (kk,c),
// then 32 FFMA2 vs SMEM float4 weights [kk][c][o].
// ---------------------------------------------------------------------------
__global__ __launch_bounds__(256, 1)
void deform_kernel(const float* __restrict__ x,
                   const float* __restrict__ w,
                   const float* __restrict__ bias) {
    extern __shared__ float Ws[];  // 9*64*64 floats = 147456 B
    const int tid = threadIdx.x;
    for (int i = tid; i < 9*64*64; i += blockDim.x) {
        int o  = i / 576;
        int r  = i % 576;
        int c  = r / 9;
        int kk = r % 9;
        Ws[kk*4096 + c*64 + o] = w[i];
    }
    __syncthreads();

    const int p   = blockIdx.x * blockDim.x + tid;
    const int b   = p >> 14;
    const int rem = p & 16383;
    const int h   = rem >> 7;
    const int wx  = rem & 127;

    unsigned long long acc[32];
    #pragma unroll
    for (int j = 0; j < 32; j++) {
        acc[j] = pack2(bias[2*j], bias[2*j+1]);
    }

    const float* xb   = x + b*(CHI*HW);
    const float* offb = g_off + b*(27*HW) + rem;

    for (int kk = 0; kk < 9; kk++) {
        const float dy = offb[(2*kk  )*HW];
        const float dx = offb[(2*kk+1)*HW];
        const float ml = offb[(18+kk)*HW];
        const float mask = 1.f / (1.f + __expf(-ml));
        const int ky = kk / 3, kx = kk % 3;
        const float py = (float)(h  - 1 + ky) + dy;
        const float px = (float)(wx - 1 + kx) + dx;
        const float fy0 = floorf(py);
        const float fx0 = floorf(px);
        const float wy  = py - fy0;
        const float wxf = px - fx0;
        const int iy0 = (int)fy0, ix0 = (int)fx0;
        const int iy1 = iy0 + 1,  ix1 = ix0 + 1;
        const float vy0 = (iy0 >= 0 && iy0 < HH) ? 1.f : 0.f;
        const float vy1 = (iy1 >= 0 && iy1 < HH) ? 1.f : 0.f;
        const float vx0 = (ix0 >= 0 && ix0 < WW) ? 1.f : 0.f;
        const float vx1 = (ix1 >= 0 && ix1 < WW) ? 1.f : 0.f;
        const int cy0 = min(max(iy0,0),HH-1), cy1 = min(max(iy1,0),HH-1);
        const int cx0 = min(max(ix0,0),WW-1), cx1 = min(max(ix1,0),WW-1);
        const float w00 = (1.f-wy)*(1.f-wxf)*vy0*vx0*mask;
        const float w01 = (1.f-wy)*wxf      *vy0*vx1*mask;
        const float w10 = wy      *(1.f-wxf)*vy1*vx0*mask;
        const float w11 = wy      *wxf      *vy1*vx1*mask;
        const int i00 = cy0*WW + cx0;
        const int i01 = cy0*WW + cx1;
        const int i10 = cy1*WW + cx0;
        const int i11 = cy1*WW + cx1;
        const float4* wkk = (const float4*)(Ws + kk*4096);
        for (int c = 0; c < 64; c++) {
            const float* xp = xb + c*HW;
            const float v = w00*xp[i00] + w01*xp[i01] + w10*xp[i10] + w11*xp[i11];
            const unsigned long long vv = pack2(v, v);
            const float4* w4 = wkk + c*16;   // 16 x 16B = 64 floats
            #pragma unroll
            for (int j = 0; j < 16; j++) {
                float4 t = w4[j];
                acc[2*j+0] = fma2(vv, pack2(t.x, t.y), acc[2*j+0]);
                acc[2*j+1] = fma2(vv, pack2(t.z, t.w), acc[2*j+1]);
            }
        }
    }
    float* yb = g_y + b*(CHO*HW) + rem;
    #pragma unroll
    for (int j = 0; j < 32; j++) {
        float lo, hi;
        unpack2(acc[j], lo, hi);
        yb[(2*j  )*HW] = lo;
        yb[(2*j+1)*HW] = hi;
    }
}

// ---------------------------------------------------------------------------
// Kernel C1: BN stats stage 1 — 8 slices per channel, float4 loads,
// deterministic per-block tree reduction. grid = 64 channels * 8 slices
// ---------------------------------------------------------------------------
__global__ __launch_bounds__(256)
void stats1_kernel() {
    const int ch    = blockIdx.x >> 3;
    const int slice = blockIdx.x & 7;       // 8 slices of 8192 elems
    const int b     = slice >> 1;           // 2 slices per batch
    const int q0    = (slice & 1) * 8192;
    const int tid   = threadIdx.x;
    const float4* src = (const float4*)(g_y + b*(CHO*HW) + ch*HW + q0);
    float s = 0.f, ss = 0.f;
    #pragma unroll
    for (int it = 0; it < 8; it++) {        // 256 threads * 8 * 4 = 8192
        float4 v = src[it*256 + tid];
        s  += v.x + v.y + v.z + v.w;
        ss += v.x*v.x + v.y*v.y + v.z*v.z + v.w*v.w;
    }
    __shared__ float sh_s[256], sh_ss[256];
    sh_s[tid] = s; sh_ss[tid] = ss;
    __syncthreads();
    for (int st = 128; st > 0; st >>= 1) {
        if (tid < st) { sh_s[tid] += sh_s[tid+st]; sh_ss[tid] += sh_ss[tid+st]; }
        __syncthreads();
    }
    if (tid == 0) {
        g_part[(ch*8 + slice)*2 + 0] = sh_s[0];
        g_part[(ch*8 + slice)*2 + 1] = sh_ss[0];
    }
}

// ---------------------------------------------------------------------------
// Kernel C2: finalize scale/shift (64 threads)
// ---------------------------------------------------------------------------
__global__ void stats2_kernel(const float* __restrict__ gamma,
                              const float* __restrict__ beta) {
    const int ch = threadIdx.x;
    if (ch >= 64) return;
    float s = 0.f, ss = 0.f;
    #pragma unroll
    for (int j = 0; j < 8; j++) {
        s  += g_part[(ch*8 + j)*2 + 0];
        ss += g_part[(ch*8 + j)*2 + 1];
    }
    const float inv  = 1.f / (float)NPIX;
    const float mean = s * inv;
    const float var  = ss * inv - mean*mean;
    const float rstd = rsqrtf(var + 1e-5f);
    const float sc   = rstd * gamma[ch];
    g_scale[ch] = sc;
    g_shift[ch] = beta[ch] - mean*sc;
}

// ---------------------------------------------------------------------------
// Kernel D: normalize + ReLU -> d_out (float4)
// ---------------------------------------------------------------------------
__global__ __launch_bounds__(256)
void norm_kernel(float4* __restrict__ out) {
    const int i = blockIdx.x * blockDim.x + threadIdx.x;   // float4 index
    const int c = (i >> 12) & 63;                          // 4096 float4 per plane
    const float sc = g_scale[c];
    const float sh = g_shift[c];
    float4 v = ((const float4*)g_y)[i];
    v.x = fmaxf(v.x*sc + sh, 0.f);
    v.y = fmaxf(v.y*sc + sh, 0.f);
    v.z = fmaxf(v.z*sc + sh, 0.f);
    v.w = fmaxf(v.w*sc + sh, 0.f);
    out[i] = v;
}

extern "C" void kernel_launch(void* const* d_in, const int* in_sizes, int n_in,
                              void* d_out, int out_size) {
    const float* x     = (const float*)d_in[0];
    const float* w_off = (const float*)d_in[1];
    const float* b_off = (const float*)d_in[2];
    const float* w     = (const float*)d_in[3];
    const float* b     = (const float*)d_in[4];
    const float* gamma = (const float*)d_in[5];
    const float* beta  = (const float*)d_in[6];

    cudaFuncSetAttribute(offset_conv_kernel,
                         cudaFuncAttributeMaxDynamicSharedMemorySize, 9*64*28*4);
    cudaFuncSetAttribute(deform_kernel,
                         cudaFuncAttributeMaxDynamicSharedMemorySize, 9*64*64*4);

    offset_conv_kernel<<<NPIX/256, 256, 9*64*28*4>>>(x, w_off, b_off);
    deform_kernel<<<NPIX/256, 256, 9*64*64*4>>>(x, w, b);
    stats1_kernel<<<64*8, 256>>>();
    stats2_kernel<<<1, 64>>>(gamma, beta);
    norm_kernel<<<(NPIX*CHO/4)/256, 256>>>((float4*)d_out);
}

// round 6
// speedup vs baseline: 1.3672x; 1.3599x over previous
#include <cuda_runtime.h>
#include <math.h>

#define CHI 64
#define CHO 64
#define HH 128
#define WW 128
#define BB 4
#define HW (HH*WW)          /* 16384 */
#define NPIX (BB*HW)        /* 65536 */

// Scratch (static device globals: allocation-free per harness rules)
__device__ float g_off[BB*27*HW];     // offset-conv output (27 ch)
__device__ float g_y[BB*CHO*HW];      // pre-BN deform-conv output
__device__ float g_part[64*8*2];      // BN stage-1 partials
__device__ float g_scale[CHO];
__device__ float g_shift[CHO];

// ---- packed f32x2 helpers (sm_103a FFMA2 path) ------------------------------
__device__ __forceinline__ unsigned long long pack2(float lo, float hi) {
    unsigned long long r;
    asm("mov.b64 %0, {%1, %2};" : "=l"(r) : "f"(lo), "f"(hi));
    return r;
}
__device__ __forceinline__ void unpack2(unsigned long long v, float& lo, float& hi) {
    asm("mov.b64 {%0, %1}, %2;" : "=f"(lo), "=f"(hi) : "l"(v));
}
__device__ __forceinline__ unsigned long long fma2(unsigned long long a,
                                                   unsigned long long b,
                                                   unsigned long long c) {
    unsigned long long d;
    asm("fma.rn.f32x2 %0, %1, %2, %3;" : "=l"(d) : "l"(a), "l"(b), "l"(c));
    return d;
}

// Per-pixel deform tap state
struct Tap {
    float w00, w01, w10, w11;
    int   i00, i01, i10, i11;
};

__device__ __forceinline__ Tap make_tap(const float* offb, int kk,
                                        int h, int wx) {
    Tap t;
    const float dy = offb[(2*kk  )*HW];
    const float dx = offb[(2*kk+1)*HW];
    const float ml = offb[(18+kk)*HW];
    const float mask = 1.f / (1.f + __expf(-ml));
    const int ky = kk / 3, kx = kk % 3;
    const float py = (float)(h  - 1 + ky) + dy;
    const float px = (float)(wx - 1 + kx) + dx;
    const float fy0 = floorf(py);
    const float fx0 = floorf(px);
    const float wy  = py - fy0;
    const float wxf = px - fx0;
    const int iy0 = (int)fy0, ix0 = (int)fx0;
    const int iy1 = iy0 + 1,  ix1 = ix0 + 1;
    const float vy0 = (iy0 >= 0 && iy0 < HH) ? 1.f : 0.f;
    const float vy1 = (iy1 >= 0 && iy1 < HH) ? 1.f : 0.f;
    const float vx0 = (ix0 >= 0 && ix0 < WW) ? 1.f : 0.f;
    const float vx1 = (ix1 >= 0 && ix1 < WW) ? 1.f : 0.f;
    const int cy0 = min(max(iy0,0),HH-1), cy1 = min(max(iy1,0),HH-1);
    const int cx0 = min(max(ix0,0),WW-1), cx1 = min(max(ix1,0),WW-1);
    t.w00 = (1.f-wy)*(1.f-wxf)*vy0*vx0*mask;
    t.w01 = (1.f-wy)*wxf      *vy0*vx1*mask;
    t.w10 = wy      *(1.f-wxf)*vy1*vx0*mask;
    t.w11 = wy      *wxf      *vy1*vx1*mask;
    t.i00 = cy0*WW + cx0;
    t.i01 = cy0*WW + cx1;
    t.i10 = cy1*WW + cx0;
    t.i11 = cy1*WW + cx1;
    return t;
}

// ---------------------------------------------------------------------------
// Kernel A: offset conv, 64 -> 27 ch, 3x3, pad 1.
// 512 threads/CTA, 1 pixel/thread, 128 CTAs = single wave.
// ---------------------------------------------------------------------------
__global__ __launch_bounds__(512)
void offset_conv_kernel(const float* __restrict__ x,
                        const float* __restrict__ w_off,
                        const float* __restrict__ b_off) {
    extern __shared__ float Wo[];  // 9*64*28 floats = 64512 B
    const int tid = threadIdx.x;
    for (int i = tid; i < 9*64*28; i += blockDim.x) {
        int kk = i / (64*28);
        int r  = i % (64*28);
        int c  = r / 28;
        int oc = r % 28;
        Wo[i] = (oc < 27) ? w_off[oc*(64*9) + c*9 + kk] : 0.f;
    }
    __syncthreads();

    const int p   = blockIdx.x * 512 + tid;
    const int b   = p >> 14;
    const int rem = p & 16383;
    const int h   = rem >> 7;
    const int wx  = rem & 127;

    unsigned long long acc[14];
    #pragma unroll
    for (int i = 0; i < 14; i++) acc[i] = 0ull;

    const float* xb = x + b * (CHI*HW);
    #pragma unroll
    for (int ky = 0; ky < 3; ky++) {
        const int yy = h + ky - 1;
        if (yy < 0 || yy >= HH) continue;
        #pragma unroll
        for (int kx = 0; kx < 3; kx++) {
            const int xx = wx + kx - 1;
            if (xx < 0 || xx >= WW) continue;
            const float* xp = xb + yy*WW + xx;
            const ulonglong2* wp = (const ulonglong2*)(Wo + (ky*3+kx)*(64*28));
            for (int c = 0; c < 64; c++) {
                const float xv = xp[c*HW];
                const unsigned long long vv = pack2(xv, xv);
                const ulonglong2* w2 = wp + c*7;   // 7 x 16B = 28 floats
                #pragma unroll
                for (int j = 0; j < 7; j++) {
                    ulonglong2 t = w2[j];
                    acc[2*j+0] = fma2(vv, t.x, acc[2*j+0]);
                    acc[2*j+1] = fma2(vv, t.y, acc[2*j+1]);
                }
            }
        }
    }
    float* ob = g_off + b*(27*HW) + rem;
    #pragma unroll
    for (int j = 0; j < 14; j++) {
        float lo, hi;
        unpack2(acc[j], lo, hi);
        const int oc = 2*j;
        ob[oc*HW] = lo + b_off[oc];
        if (oc + 1 < 27) ob[(oc+1)*HW] = hi + b_off[oc+1];
    }
}

// ---------------------------------------------------------------------------
// Kernel B: deformable sampling + 576x64 contraction.
// 256 threads/CTA, 2 pixels/thread (rows h and h+64 of same image) sharing
// all weight LDS; 128 CTAs = single wave. 64 acc pairs per pixel.
// ---------------------------------------------------------------------------
__global__ __launch_bounds__(256, 1)
void deform_kernel(const float* __restrict__ x,
                   const float* __restrict__ w,
                   const float* __restrict__ bias) {
    extern __shared__ float Ws[];  // 9*64*64 floats = 147456 B
    const int tid = threadIdx.x;
    for (int i = tid; i < 9*64*64; i += blockDim.x) {
        int o  = i / 576;
        int r  = i % 576;
        int c  = r / 9;
        int kk = r % 9;
        Ws[kk*4096 + c*64 + o] = w[i];
    }
    __syncthreads();

    const int cta  = blockIdx.x;        // 0..127
    const int b    = cta >> 5;          // 32 CTAs per image
    const int remA = (cta & 31)*256 + tid;   // rows 0..63
    const int remB = remA + 8192;            // rows 64..127
    const int hA   = remA >> 7;
    const int wx   = remA & 127;
    const int hB   = hA + 64;

    unsigned long long accA[32], accB[32];
    #pragma unroll
    for (int j = 0; j < 32; j++) {
        const unsigned long long bi = pack2(bias[2*j], bias[2*j+1]);
        accA[j] = bi;
        accB[j] = bi;
    }

    const float* xb    = x + b*(CHI*HW);
    const float* offbA = g_off + b*(27*HW) + remA;
    const float* offbB = g_off + b*(27*HW) + remB;

    for (int kk = 0; kk < 9; kk++) {
        const Tap tA = make_tap(offbA, kk, hA, wx);
        const Tap tB = make_tap(offbB, kk, hB, wx);
        const ulonglong2* wkk = (const ulonglong2*)(Ws + kk*4096);
        for (int c = 0; c < 64; c++) {
            const float* xp = xb + c*HW;
            const float vA = tA.w00*xp[tA.i00] + tA.w01*xp[tA.i01]
                           + tA.w10*xp[tA.i10] + tA.w11*xp[tA.i11];
            const float vB = tB.w00*xp[tB.i00] + tB.w01*xp[tB.i01]
                           + tB.w10*xp[tB.i10] + tB.w11*xp[tB.i11];
            const unsigned long long vvA = pack2(vA, vA);
            const unsigned long long vvB = pack2(vB, vB);
            const ulonglong2* w2 = wkk + c*16;   // 16 x 16B = 64 floats
            #pragma unroll
            for (int j = 0; j < 16; j++) {
                ulonglong2 t = w2[j];
                accA[2*j+0] = fma2(vvA, t.x, accA[2*j+0]);
                accA[2*j+1] = fma2(vvA, t.y, accA[2*j+1]);
                accB[2*j+0] = fma2(vvB, t.x, accB[2*j+0]);
                accB[2*j+1] = fma2(vvB, t.y, accB[2*j+1]);
            }
        }
    }
    float* ybA = g_y + b*(CHO*HW) + remA;
    float* ybB = g_y + b*(CHO*HW) + remB;
    #pragma unroll
    for (int j = 0; j < 32; j++) {
        float lo, hi;
        unpack2(accA[j], lo, hi);
        ybA[(2*j  )*HW] = lo;
        ybA[(2*j+1)*HW] = hi;
        unpack2(accB[j], lo, hi);
        ybB[(2*j  )*HW] = lo;
        ybB[(2*j+1)*HW] = hi;
    }
}

// ---------------------------------------------------------------------------
// Kernel C1: BN stats stage 1 — 8 slices per channel, float4 loads,
// deterministic per-block tree reduction. grid = 64 channels * 8 slices
// ---------------------------------------------------------------------------
__global__ __launch_bounds__(256)
void stats1_kernel() {
    const int ch    = blockIdx.x >> 3;
    const int slice = blockIdx.x & 7;
    const int b     = slice >> 1;
    const int q0    = (slice & 1) * 8192;
    const int tid   = threadIdx.x;
    const float4* src = (const float4*)(g_y + b*(CHO*HW) + ch*HW + q0);
    float s = 0.f, ss = 0.f;
    #pragma unroll
    for (int it = 0; it < 8; it++) {
        float4 v = src[it*256 + tid];
        s  += v.x + v.y + v.z + v.w;
        ss += v.x*v.x + v.y*v.y + v.z*v.z + v.w*v.w;
    }
    __shared__ float sh_s[256], sh_ss[256];
    sh_s[tid] = s; sh_ss[tid] = ss;
    __syncthreads();
    for (int st = 128; st > 0; st >>= 1) {
        if (tid < st) { sh_s[tid] += sh_s[tid+st]; sh_ss[tid] += sh_ss[tid+st]; }
        __syncthreads();
    }
    if (tid == 0) {
        g_part[(ch*8 + slice)*2 + 0] = sh_s[0];
        g_part[(ch*8 + slice)*2 + 1] = sh_ss[0];
    }
}

// ---------------------------------------------------------------------------
// Kernel C2: finalize scale/shift (64 threads)
// ---------------------------------------------------------------------------
__global__ void stats2_kernel(const float* __restrict__ gamma,
                              const float* __restrict__ beta) {
    const int ch = threadIdx.x;
    if (ch >= 64) return;
    float s = 0.f, ss = 0.f;
    #pragma unroll
    for (int j = 0; j < 8; j++) {
        s  += g_part[(ch*8 + j)*2 + 0];
        ss += g_part[(ch*8 + j)*2 + 1];
    }
    const float inv  = 1.f / (float)NPIX;
    const float mean = s * inv;
    const float var  = ss * inv - mean*mean;
    const float rstd = rsqrtf(var + 1e-5f);
    const float sc   = rstd * gamma[ch];
    g_scale[ch] = sc;
    g_shift[ch] = beta[ch] - mean*sc;
}

// ---------------------------------------------------------------------------
// Kernel D: normalize + ReLU -> d_out; 2 float4 per thread for MLP.
// ---------------------------------------------------------------------------
__global__ __launch_bounds__(256)
void norm_kernel(float4* __restrict__ out) {
    const int i0 = blockIdx.x * 256 + threadIdx.x;       // first float4 index
    const int HALF = (NPIX*CHO/4)/2;                     // 524288 float4
    #pragma unroll
    for (int k = 0; k < 2; k++) {
        const int i = i0 + k*HALF;
        const int c = (i >> 12) & 63;                    // 4096 float4 / plane
        const float sc = g_scale[c];
        const float sh = g_shift[c];
        float4 v = ((const float4*)g_y)[i];
        v.x = fmaxf(v.x*sc + sh, 0.f);
        v.y = fmaxf(v.y*sc + sh, 0.f);
        v.z = fmaxf(v.z*sc + sh, 0.f);
        v.w = fmaxf(v.w*sc + sh, 0.f);
        out[i] = v;
    }
}

extern "C" void kernel_launch(void* const* d_in, const int* in_sizes, int n_in,
                              void* d_out, int out_size) {
    const float* x     = (const float*)d_in[0];
    const float* w_off = (const float*)d_in[1];
    const float* b_off = (const float*)d_in[2];
    const float* w     = (const float*)d_in[3];
    const float* b     = (const float*)d_in[4];
    const float* gamma = (const float*)d_in[5];
    const float* beta  = (const float*)d_in[6];

    cudaFuncSetAttribute(offset_conv_kernel,
                         cudaFuncAttributeMaxDynamicSharedMemorySize, 9*64*28*4);
    cudaFuncSetAttribute(deform_kernel,
                         cudaFuncAttributeMaxDynamicSharedMemorySize, 9*64*64*4);

    offset_conv_kernel<<<NPIX/512, 512, 9*64*28*4>>>(x, w_off, b_off);
    deform_kernel<<<128, 256, 9*64*64*4>>>(x, w, b);
    stats1_kernel<<<64*8, 256>>>();
    stats2_kernel<<<1, 64>>>(gamma, beta);
    norm_kernel<<<(NPIX*CHO/4/2)/256, 256>>>((float4*)d_out);
}

// round 7
// speedup vs baseline: 1.4444x; 1.0565x over previous
#include <cuda_runtime.h>
#include <math.h>

#define CHI 64
#define CHO 64
#define HH 128
#define WW 128
#define BB 4
#define HW (HH*WW)          /* 16384 */
#define NPIX (BB*HW)        /* 65536 */

// Scratch (static device globals: allocation-free per harness rules)
__device__ float g_off[BB*27*HW];     // offset-conv output (27 ch)
__device__ float g_y[BB*CHO*HW];      // pre-BN deform-conv output
__device__ float g_part[64*8*2];      // BN stage-1 partials
__device__ float g_scale[CHO];
__device__ float g_shift[CHO];

// ---- packed f32x2 helpers (sm_103a FFMA2 path) ------------------------------
__device__ __forceinline__ unsigned long long pack2(float lo, float hi) {
    unsigned long long r;
    asm("mov.b64 %0, {%1, %2};" : "=l"(r) : "f"(lo), "f"(hi));
    return r;
}
__device__ __forceinline__ void unpack2(unsigned long long v, float& lo, float& hi) {
    asm("mov.b64 {%0, %1}, %2;" : "=f"(lo), "=f"(hi) : "l"(v));
}
__device__ __forceinline__ unsigned long long fma2(unsigned long long a,
                                                   unsigned long long b,
                                                   unsigned long long c) {
    unsigned long long d;
    asm("fma.rn.f32x2 %0, %1, %2, %3;" : "=l"(d) : "l"(a), "l"(b), "l"(c));
    return d;
}

// Per-pixel deform tap state
struct Tap {
    float w00, w01, w10, w11;
    int   i00, i01, i10, i11;
};

__device__ __forceinline__ Tap make_tap(const float* offb, int kk,
                                        int h, int wx) {
    Tap t;
    const float dy = offb[(2*kk  )*HW];
    const float dx = offb[(2*kk+1)*HW];
    const float ml = offb[(18+kk)*HW];
    const float mask = 1.f / (1.f + __expf(-ml));
    const int ky = kk / 3, kx = kk % 3;
    const float py = (float)(h  - 1 + ky) + dy;
    const float px = (float)(wx - 1 + kx) + dx;
    const float fy0 = floorf(py);
    const float fx0 = floorf(px);
    const float wy  = py - fy0;
    const float wxf = px - fx0;
    const int iy0 = (int)fy0, ix0 = (int)fx0;
    const int iy1 = iy0 + 1,  ix1 = ix0 + 1;
    const float vy0 = (iy0 >= 0 && iy0 < HH) ? 1.f : 0.f;
    const float vy1 = (iy1 >= 0 && iy1 < HH) ? 1.f : 0.f;
    const float vx0 = (ix0 >= 0 && ix0 < WW) ? 1.f : 0.f;
    const float vx1 = (ix1 >= 0 && ix1 < WW) ? 1.f : 0.f;
    const int cy0 = min(max(iy0,0),HH-1), cy1 = min(max(iy1,0),HH-1);
    const int cx0 = min(max(ix0,0),WW-1), cx1 = min(max(ix1,0),WW-1);
    t.w00 = (1.f-wy)*(1.f-wxf)*vy0*vx0*mask;
    t.w01 = (1.f-wy)*wxf      *vy0*vx1*mask;
    t.w10 = wy      *(1.f-wxf)*vy1*vx0*mask;
    t.w11 = wy      *wxf      *vy1*vx1*mask;
    t.i00 = cy0*WW + cx0;
    t.i01 = cy0*WW + cx1;
    t.i10 = cy1*WW + cx0;
    t.i11 = cy1*WW + cx1;
    return t;
}

// ---------------------------------------------------------------------------
// Kernel A: offset conv, 64 -> 27 ch, 3x3, pad 1.
// 512 threads/CTA, 1 pixel/thread, 128 CTAs = single wave.
// Channel loop double-buffers xv so LDG latency overlaps the FFMA2 block.
// ---------------------------------------------------------------------------
__global__ __launch_bounds__(512)
void offset_conv_kernel(const float* __restrict__ x,
                        const float* __restrict__ w_off,
                        const float* __restrict__ b_off) {
    extern __shared__ float Wo[];  // 9*64*28 floats = 64512 B
    const int tid = threadIdx.x;
    for (int i = tid; i < 9*64*28; i += blockDim.x) {
        int kk = i / (64*28);
        int r  = i % (64*28);
        int c  = r / 28;
        int oc = r % 28;
        Wo[i] = (oc < 27) ? w_off[oc*(64*9) + c*9 + kk] : 0.f;
    }
    __syncthreads();

    const int p   = blockIdx.x * 512 + tid;
    const int b   = p >> 14;
    const int rem = p & 16383;
    const int h   = rem >> 7;
    const int wx  = rem & 127;

    unsigned long long acc[14];
    #pragma unroll
    for (int i = 0; i < 14; i++) acc[i] = 0ull;

    const float* xb = x + b * (CHI*HW);
    #pragma unroll
    for (int ky = 0; ky < 3; ky++) {
        const int yy = h + ky - 1;
        if (yy < 0 || yy >= HH) continue;
        #pragma unroll
        for (int kx = 0; kx < 3; kx++) {
            const int xx = wx + kx - 1;
            if (xx < 0 || xx >= WW) continue;
            const float* xp = xb + yy*WW + xx;
            const ulonglong2* wp = (const ulonglong2*)(Wo + (ky*3+kx)*(64*28));
            float cur = xp[0];
            for (int c = 0; c < 64; c++) {
                const int cn = (c + 1) & 63;       // wraps on last iter (benign)
                const float nxt = xp[cn*HW];       // prefetch c+1
                const unsigned long long vv = pack2(cur, cur);
                const ulonglong2* w2 = wp + c*7;   // 7 x 16B = 28 floats
                #pragma unroll
                for (int j = 0; j < 7; j++) {
                    ulonglong2 t = w2[j];
                    acc[2*j+0] = fma2(vv, t.x, acc[2*j+0]);
                    acc[2*j+1] = fma2(vv, t.y, acc[2*j+1]);
                }
                cur = nxt;
            }
        }
    }
    float* ob = g_off + b*(27*HW) + rem;
    #pragma unroll
    for (int j = 0; j < 14; j++) {
        float lo, hi;
        unpack2(acc[j], lo, hi);
        const int oc = 2*j;
        ob[oc*HW] = lo + b_off[oc];
        if (oc + 1 < 27) ob[(oc+1)*HW] = hi + b_off[oc+1];
    }
}

// ---------------------------------------------------------------------------
// Kernel B: deformable sampling + 576x64 contraction.
// 256 threads/CTA, 2 pixels/thread (rows h and h+64) sharing weight LDS;
// 128 CTAs = single wave. Gather loads double-buffered over the channel loop
// so the 8 scattered LDGs of c+1 overlap the 64-FFMA2 block of c.
// ---------------------------------------------------------------------------
__global__ __launch_bounds__(256, 1)
void deform_kernel(const float* __restrict__ x,
                   const float* __restrict__ w,
                   const float* __restrict__ bias) {
    extern __shared__ float Ws[];  // 9*64*64 floats = 147456 B
    const int tid = threadIdx.x;
    for (int i = tid; i < 9*64*64; i += blockDim.x) {
        int o  = i / 576;
        int r  = i % 576;
        int c  = r / 9;
        int kk = r % 9;
        Ws[kk*4096 + c*64 + o] = w[i];
    }
    __syncthreads();

    const int cta  = blockIdx.x;        // 0..127
    const int b    = cta >> 5;          // 32 CTAs per image
    const int remA = (cta & 31)*256 + tid;   // rows 0..63
    const int remB = remA + 8192;            // rows 64..127
    const int hA   = remA >> 7;
    const int wx   = remA & 127;
    const int hB   = hA + 64;

    unsigned long long accA[32], accB[32];
    #pragma unroll
    for (int j = 0; j < 32; j++) {
        const unsigned long long bi = pack2(bias[2*j], bias[2*j+1]);
        accA[j] = bi;
        accB[j] = bi;
    }

    const float* xb    = x + b*(CHI*HW);
    const float* offbA = g_off + b*(27*HW) + remA;
    const float* offbB = g_off + b*(27*HW) + remB;

    for (int kk = 0; kk < 9; kk++) {
        const Tap tA = make_tap(offbA, kk, hA, wx);
        const Tap tB = make_tap(offbB, kk, hB, wx);
        const float* pA00 = xb + tA.i00;
        const float* pA01 = xb + tA.i01;
        const float* pA10 = xb + tA.i10;
        const float* pA11 = xb + tA.i11;
        const float* pB00 = xb + tB.i00;
        const float* pB01 = xb + tB.i01;
        const float* pB10 = xb + tB.i10;
        const float* pB11 = xb + tB.i11;
        // prime c = 0
        float cA00 = pA00[0], cA01 = pA01[0], cA10 = pA10[0], cA11 = pA11[0];
        float cB00 = pB00[0], cB01 = pB01[0], cB10 = pB10[0], cB11 = pB11[0];
        const ulonglong2* wkk = (const ulonglong2*)(Ws + kk*4096);
        for (int c = 0; c < 64; c++) {
            const int co = ((c + 1) & 63) * HW;   // prefetch offset (wraps, benign)
            const float nA00 = pA00[co], nA01 = pA01[co];
            const float nA10 = pA10[co], nA11 = pA11[co];
            const float nB00 = pB00[co], nB01 = pB01[co];
            const float nB10 = pB10[co], nB11 = pB11[co];

            const float vA = tA.w00*cA00 + tA.w01*cA01 + tA.w10*cA10 + tA.w11*cA11;
            const float vB = tB.w00*cB00 + tB.w01*cB01 + tB.w10*cB10 + tB.w11*cB11;
            const unsigned long long vvA = pack2(vA, vA);
            const unsigned long long vvB = pack2(vB, vB);
            const ulonglong2* w2 = wkk + c*16;   // 16 x 16B = 64 floats
            #pragma unroll
            for (int j = 0; j < 16; j++) {
                ulonglong2 t = w2[j];
                accA[2*j+0] = fma2(vvA, t.x, accA[2*j+0]);
                accA[2*j+1] = fma2(vvA, t.y, accA[2*j+1]);
                accB[2*j+0] = fma2(vvB, t.x, accB[2*j+0]);
                accB[2*j+1] = fma2(vvB, t.y, accB[2*j+1]);
            }
            cA00 = nA00; cA01 = nA01; cA10 = nA10; cA11 = nA11;
            cB00 = nB00; cB01 = nB01; cB10 = nB10; cB11 = nB11;
        }
    }
    float* ybA = g_y + b*(CHO*HW) + remA;
    float* ybB = g_y + b*(CHO*HW) + remB;
    #pragma unroll
    for (int j = 0; j < 32; j++) {
        float lo, hi;
        unpack2(accA[j], lo, hi);
        ybA[(2*j  )*HW] = lo;
        ybA[(2*j+1)*HW] = hi;
        unpack2(accB[j], lo, hi);
        ybB[(2*j  )*HW] = lo;
        ybB[(2*j+1)*HW] = hi;
    }
}

// ---------------------------------------------------------------------------
// Kernel C1: BN stats stage 1 — 8 slices per channel, float4 loads,
// deterministic per-block tree reduction. grid = 64 channels * 8 slices
// ---------------------------------------------------------------------------
__global__ __launch_bounds__(256)
void stats1_kernel() {
    const int ch    = blockIdx.x >> 3;
    const int slice = blockIdx.x & 7;
    const int b     = slice >> 1;
    const int q0    = (slice & 1) * 8192;
    const int tid   = threadIdx.x;
    const float4* src = (const float4*)(g_y + b*(CHO*HW) + ch*HW + q0);
    float s = 0.f, ss = 0.f;
    #pragma unroll
    for (int it = 0; it < 8; it++) {
        float4 v = src[it*256 + tid];
        s  += v.x + v.y + v.z + v.w;
        ss += v.x*v.x + v.y*v.y + v.z*v.z + v.w*v.w;
    }
    __shared__ float sh_s[256], sh_ss[256];
    sh_s[tid] = s; sh_ss[tid] = ss;
    __syncthreads();
    for (int st = 128; st > 0; st >>= 1) {
        if (tid < st) { sh_s[tid] += sh_s[tid+st]; sh_ss[tid] += sh_ss[tid+st]; }
        __syncthreads();
    }
    if (tid == 0) {
        g_part[(ch*8 + slice)*2 + 0] = sh_s[0];
        g_part[(ch*8 + slice)*2 + 1] = sh_ss[0];
    }
}

// ---------------------------------------------------------------------------
// Kernel C2: finalize scale/shift (64 threads)
// ---------------------------------------------------------------------------
__global__ void stats2_kernel(const float* __restrict__ gamma,
                              const float* __restrict__ beta) {
    const int ch = threadIdx.x;
    if (ch >= 64) return;
    float s = 0.f, ss = 0.f;
    #pragma unroll
    for (int j = 0; j < 8; j++) {
        s  += g_part[(ch*8 + j)*2 + 0];
        ss += g_part[(ch*8 + j)*2 + 1];
    }
    const float inv  = 1.f / (float)NPIX;
    const float mean = s * inv;
    const float var  = ss * inv - mean*mean;
    const float rstd = rsqrtf(var + 1e-5f);
    const float sc   = rstd * gamma[ch];
    g_scale[ch] = sc;
    g_shift[ch] = beta[ch] - mean*sc;
}

// ---------------------------------------------------------------------------
// Kernel D: normalize + ReLU -> d_out; 2 float4 per thread for MLP.
// ---------------------------------------------------------------------------
__global__ __launch_bounds__(256)
void norm_kernel(float4* __restrict__ out) {
    const int i0 = blockIdx.x * 256 + threadIdx.x;       // first float4 index
    const int HALF = (NPIX*CHO/4)/2;                     // 524288 float4
    #pragma unroll
    for (int k = 0; k < 2; k++) {
        const int i = i0 + k*HALF;
        const int c = (i >> 12) & 63;                    // 4096 float4 / plane
        const float sc = g_scale[c];
        const float sh = g_shift[c];
        float4 v = ((const float4*)g_y)[i];
        v.x = fmaxf(v.x*sc + sh, 0.f);
        v.y = fmaxf(v.y*sc + sh, 0.f);
        v.z = fmaxf(v.z*sc + sh, 0.f);
        v.w = fmaxf(v.w*sc + sh, 0.f);
        out[i] = v;
    }
}

extern "C" void kernel_launch(void* const* d_in, const int* in_sizes, int n_in,
                              void* d_out, int out_size) {
    const float* x     = (const float*)d_in[0];
    const float* w_off = (const float*)d_in[1];
    const float* b_off = (const float*)d_in[2];
    const float* w     = (const float*)d_in[3];
    const float* b     = (const float*)d_in[4];
    const float* gamma = (const float*)d_in[5];
    const float* beta  = (const float*)d_in[6];

    cudaFuncSetAttribute(offset_conv_kernel,
                         cudaFuncAttributeMaxDynamicSharedMemorySize, 9*64*28*4);
    cudaFuncSetAttribute(deform_kernel,
                         cudaFuncAttributeMaxDynamicSharedMemorySize, 9*64*64*4);

    offset_conv_kernel<<<NPIX/512, 512, 9*64*28*4>>>(x, w_off, b_off);
    deform_kernel<<<128, 256, 9*64*64*4>>>(x, w, b);
    stats1_kernel<<<64*8, 256>>>();
    stats2_kernel<<<1, 64>>>(gamma, beta);
    norm_kernel<<<(NPIX*CHO/4/2)/256, 256>>>((float4*)d_out);
}

// round 10
// speedup vs baseline: 1.9736x; 1.3664x over previous
#include <cuda_runtime.h>
#include <math.h>
#include <stdint.h>

#define CHI 64
#define CHO 64
#define HH 128
#define WW 128
#define BB 4
#define HW (HH*WW)          /* 16384 */
#define NPIX (BB*HW)        /* 65536 */

// Scratch (static device globals: allocation-free per harness rules)
__device__ float g_off[BB*27*HW];     // offset-conv output (27 ch)
__device__ float g_y[BB*CHO*HW];      // pre-BN deform-conv output
__device__ float g_part[64*8*2];      // BN stage-1 partials
__device__ float g_scale[CHO];
__device__ float g_shift[CHO];

// ---- packed f32x2 helpers (offset conv) ------------------------------------
__device__ __forceinline__ unsigned long long pack2(float lo, float hi) {
    unsigned long long r;
    asm("mov.b64 %0, {%1, %2};" : "=l"(r) : "f"(lo), "f"(hi));
    return r;
}
__device__ __forceinline__ void unpack2(unsigned long long v, float& lo, float& hi) {
    asm("mov.b64 {%0, %1}, %2;" : "=f"(lo), "=f"(hi) : "l"(v));
}
__device__ __forceinline__ unsigned long long fma2(unsigned long long a,
                                                   unsigned long long b,
                                                   unsigned long long c) {
    unsigned long long d;
    asm("fma.rn.f32x2 %0, %1, %2, %3;" : "=l"(d) : "l"(a), "l"(b), "l"(c));
    return d;
}

// ---- tf32 mma.sync helpers (baseline PTX, valid at target sm_103) ----------
__device__ __forceinline__ uint32_t f2tf32(float v) {
    uint32_t r;
    asm("cvt.rna.tf32.f32 %0, %1;" : "=r"(r) : "f"(v));
    return r;
}
__device__ __forceinline__ void mma_tf32(float* d, const uint32_t* a,
                                         const uint32_t* b) {
    asm volatile(
        "mma.sync.aligned.m16n8k8.row.col.f32.tf32.tf32.f32 "
        "{%0,%1,%2,%3}, {%4,%5,%6,%7}, {%8,%9}, {%0,%1,%2,%3};"
        : "+f"(d[0]), "+f"(d[1]), "+f"(d[2]), "+f"(d[3])
        : "r"(a[0]), "r"(a[1]), "r"(a[2]), "r"(a[3]), "r"(b[0]), "r"(b[1]));
}

// Per-pixel deform tap state
struct Tap {
    float w00, w01, w10, w11;
    int   i00, i01, i10, i11;
};

__device__ __forceinline__ Tap make_tap(const float* offb, int kk, int h, int wx) {
    Tap t;
    const float dy = offb[(2*kk  )*HW];
    const float dx = offb[(2*kk+1)*HW];
    const float ml = offb[(18+kk)*HW];
    const float mask = 1.f / (1.f + __expf(-ml));
    const int ky = kk / 3, kx = kk % 3;
    const float py = (float)(h  - 1 + ky) + dy;
    const float px = (float)(wx - 1 + kx) + dx;
    const float fy0 = floorf(py);
    const float fx0 = floorf(px);
    const float wy  = py - fy0;
    const float wxf = px - fx0;
    const int iy0 = (int)fy0, ix0 = (int)fx0;
    const int iy1 = iy0 + 1,  ix1 = ix0 + 1;
    const float vy0 = (iy0 >= 0 && iy0 < HH) ? 1.f : 0.f;
    const float vy1 = (iy1 >= 0 && iy1 < HH) ? 1.f : 0.f;
    const float vx0 = (ix0 >= 0 && ix0 < WW) ? 1.f : 0.f;
    const float vx1 = (ix1 >= 0 && ix1 < WW) ? 1.f : 0.f;
    const int cy0 = min(max(iy0,0),HH-1), cy1 = min(max(iy1,0),HH-1);
    const int cx0 = min(max(ix0,0),WW-1), cx1 = min(max(ix1,0),WW-1);
    t.w00 = (1.f-wy)*(1.f-wxf)*vy0*vx0*mask;
    t.w01 = (1.f-wy)*wxf      *vy0*vx1*mask;
    t.w10 = wy      *(1.f-wxf)*vy1*vx0*mask;
    t.w11 = wy      *wxf      *vy1*vx1*mask;
    t.i00 = cy0*WW + cx0;
    t.i01 = cy0*WW + cx1;
    t.i10 = cy1*WW + cx0;
    t.i11 = cy1*WW + cx1;
    return t;
}

// ---------------------------------------------------------------------------
// Kernel A: offset conv (scalar FFMA2, unchanged — passing since R6)
// ---------------------------------------------------------------------------
__global__ __launch_bounds__(512)
void offset_conv_kernel(const float* __restrict__ x,
                        const float* __restrict__ w_off,
                        const float* __restrict__ b_off) {
    extern __shared__ float Wo[];  // 9*64*28 floats
    const int tid = threadIdx.x;
    for (int i = tid; i < 9*64*28; i += blockDim.x) {
        int kk = i / (64*28);
        int r  = i % (64*28);
        int c  = r / 28;
        int oc = r % 28;
        Wo[i] = (oc < 27) ? w_off[oc*(64*9) + c*9 + kk] : 0.f;
    }
    __syncthreads();

    const int p   = blockIdx.x * 512 + tid;
    const int b   = p >> 14;
    const int rem = p & 16383;
    const int h   = rem >> 7;
    const int wx  = rem & 127;

    unsigned long long acc[14];
    #pragma unroll
    for (int i = 0; i < 14; i++) acc[i] = 0ull;

    const float* xb = x + b * (CHI*HW);
    #pragma unroll
    for (int ky = 0; ky < 3; ky++) {
        const int yy = h + ky - 1;
        if (yy < 0 || yy >= HH) continue;
        #pragma unroll
        for (int kx = 0; kx < 3; kx++) {
            const int xx = wx + kx - 1;
            if (xx < 0 || xx >= WW) continue;
            const float* xp = xb + yy*WW + xx;
            const ulonglong2* wp = (const ulonglong2*)(Wo + (ky*3+kx)*(64*28));
            float cur = xp[0];
            for (int c = 0; c < 64; c++) {
                const int cn = (c + 1) & 63;
                const float nxt = xp[cn*HW];
                const unsigned long long vv = pack2(cur, cur);
                const ulonglong2* w2 = wp + c*7;
                #pragma unroll
                for (int j = 0; j < 7; j++) {
                    ulonglong2 t = w2[j];
                    acc[2*j+0] = fma2(vv, t.x, acc[2*j+0]);
                    acc[2*j+1] = fma2(vv, t.y, acc[2*j+1]);
                }
                cur = nxt;
            }
        }
    }
    float* ob = g_off + b*(27*HW) + rem;
    #pragma unroll
    for (int j = 0; j < 14; j++) {
        float lo, hi;
        unpack2(acc[j], lo, hi);
        const int oc = 2*j;
        ob[oc*HW] = lo + b_off[oc];
        if (oc + 1 < 27) ob[(oc+1)*HW] = hi + b_off[oc+1];
    }
}

// ---------------------------------------------------------------------------
// Kernel B: deform gather + tf32 mma.sync contraction.
// 256 CTAs x 256 threads, 2 CTAs/SM. Per CTA: 256 pixels (M=256), N=64,
// K accumulated over 9 taps x 64 channels. Each warp: 32 pixels x 64 out.
// SMEM: V_T[c=64][px pitch 264] (tf32 bits), W_s[o=64][c pitch 68].
// ---------------------------------------------------------------------------
#define VPAD 264
#define WPAD 68
#define W_OFF (64*VPAD)                 /* uint32 offset of W_s */
#define DSMEM ((64*VPAD + 64*WPAD) * 4) /* 84992 bytes */

__global__ __launch_bounds__(256, 2)
void deform_mma_kernel(const float* __restrict__ x,
                       const float* __restrict__ w,
                       const float* __restrict__ bias) {
    extern __shared__ uint32_t sm[];
    uint32_t* Vt = sm;           // [64][VPAD]
    uint32_t* Ws = sm + W_OFF;   // [64][WPAD]

    const int tid  = threadIdx.x;
    const int warp = tid >> 5;
    const int lane = tid & 31;
    const int gr   = lane >> 2;   // groupID 0..7
    const int gc   = lane & 3;    // threadID_in_group 0..3

    const int p    = blockIdx.x * 256 + tid;
    const int b    = p >> 14;
    const int rem  = p & 16383;
    const int h    = rem >> 7;
    const int wx   = rem & 127;
    const int remBase = (int)(blockIdx.x & 63) * 256;   // 64 blocks per image

    const float* xb   = x + b*(CHI*HW);
    const float* offb = g_off + b*(27*HW) + rem;

    float acc[2][8][4];
    #pragma unroll
    for (int mt = 0; mt < 2; mt++)
        #pragma unroll
        for (int n = 0; n < 8; n++)
            #pragma unroll
            for (int q = 0; q < 4; q++)
                acc[mt][n][q] = 0.f;

    for (int kk = 0; kk < 9; kk++) {
        // Stage W[kk] -> Ws[o][c]  (4096 elems, 256 threads x 16)
        #pragma unroll
        for (int j = 0; j < 16; j++) {
            const int i = tid + j*256;
            const int o = i >> 6;
            const int c = i & 63;
            Ws[o*WPAD + c] = f2tf32(w[o*576 + c*9 + kk]);
        }
        // Gather: this thread's pixel, all 64 channels -> Vt[c][tid]
        {
            const Tap tp = make_tap(offb, kk, h, wx);
            const float* p00 = xb + tp.i00;
            const float* p01 = xb + tp.i01;
            const float* p10 = xb + tp.i10;
            const float* p11 = xb + tp.i11;
            #pragma unroll 8
            for (int c = 0; c < 64; c++) {
                const int off = c*HW;
                const float v = tp.w00*p00[off] + tp.w01*p01[off]
                              + tp.w10*p10[off] + tp.w11*p11[off];
                Vt[c*VPAD + tid] = f2tf32(v);
            }
        }
        __syncthreads();

        // MMA: warp covers pixels [warp*32, warp*32+32), all 64 outputs
        const int m0 = warp * 32;
        #pragma unroll
        for (int kc = 0; kc < 8; kc++) {
            const int k0 = kc * 8;
            uint32_t bf[8][2];
            #pragma unroll
            for (int n = 0; n < 8; n++) {
                bf[n][0] = Ws[(n*8 + gr)*WPAD + k0 + gc];
                bf[n][1] = Ws[(n*8 + gr)*WPAD + k0 + gc + 4];
            }
            uint32_t af[2][4];
            #pragma unroll
            for (int mt = 0; mt < 2; mt++) {
                const int m = m0 + mt*16;
                af[mt][0] = Vt[(k0 + gc    )*VPAD + m + gr];
                af[mt][1] = Vt[(k0 + gc    )*VPAD + m + gr + 8];
                af[mt][2] = Vt[(k0 + gc + 4)*VPAD + m + gr];
                af[mt][3] = Vt[(k0 + gc + 4)*VPAD + m + gr + 8];
            }
            #pragma unroll
            for (int mt = 0; mt < 2; mt++)
                #pragma unroll
                for (int n = 0; n < 8; n++)
                    mma_tf32(acc[mt][n], af[mt], bf[n]);
        }
        __syncthreads();   // V/W free for next kk
    }

    // Epilogue: C-fragments -> g_y (+ bias)
    // C layout: c0=(gr, 2gc), c1=(gr, 2gc+1), c2=(gr+8, 2gc), c3=(gr+8, 2gc+1)
    float* yb = g_y + b*(CHO*HW);
    const int m0 = warp * 32;
    const int o0 = gc * 2;
    #pragma unroll
    for (int mt = 0; mt < 2; mt++) {
        const int r0 = remBase + m0 + mt*16 + gr;
        #pragma unroll
        for (int n = 0; n < 8; n++) {
            const int oa = n*8 + o0;
            const float b0 = bias[oa];
            const float b1 = bias[oa+1];
            yb[ oa   *HW + r0    ] = acc[mt][n][0] + b0;
            yb[(oa+1)*HW + r0    ] = acc[mt][n][1] + b1;
            yb[ oa   *HW + r0 + 8] = acc[mt][n][2] + b0;
            yb[(oa+1)*HW + r0 + 8] = acc[mt][n][3] + b1;
        }
    }
}

// ---------------------------------------------------------------------------
// Kernel C1: BN stats stage 1
// ---------------------------------------------------------------------------
__global__ __launch_bounds__(256)
void stats1_kernel() {
    const int ch    = blockIdx.x >> 3;
    const int slice = blockIdx.x & 7;
    const int b     = slice >> 1;
    const int q0    = (slice & 1) * 8192;
    const int tid   = threadIdx.x;
    const float4* src = (const float4*)(g_y + b*(CHO*HW) + ch*HW + q0);
    float s = 0.f, ss = 0.f;
    #pragma unroll
    for (int it = 0; it < 8; it++) {
        float4 v = src[it*256 + tid];
        s  += v.x + v.y + v.z + v.w;
        ss += v.x*v.x + v.y*v.y + v.z*v.z + v.w*v.w;
    }
    __shared__ float sh_s[256], sh_ss[256];
    sh_s[tid] = s; sh_ss[tid] = ss;
    __syncthreads();
    for (int st = 128; st > 0; st >>= 1) {
        if (tid < st) { sh_s[tid] += sh_s[tid+st]; sh_ss[tid] += sh_ss[tid+st]; }
        __syncthreads();
    }
    if (tid == 0) {
        g_part[(ch*8 + slice)*2 + 0] = sh_s[0];
        g_part[(ch*8 + slice)*2 + 1] = sh_ss[0];
    }
}

// ---------------------------------------------------------------------------
// Kernel C2: finalize scale/shift
// ---------------------------------------------------------------------------
__global__ void stats2_kernel(const float* __restrict__ gamma,
                              const float* __restrict__ beta) {
    const int ch = threadIdx.x;
    if (ch >= 64) return;
    float s = 0.f, ss = 0.f;
    #pragma unroll
    for (int j = 0; j < 8; j++) {
        s  += g_part[(ch*8 + j)*2 + 0];
        ss += g_part[(ch*8 + j)*2 + 1];
    }
    const float inv  = 1.f / (float)NPIX;
    const float mean = s * inv;
    const float var  = ss * inv - mean*mean;
    const float rstd = rsqrtf(var + 1e-5f);
    const float sc   = rstd * gamma[ch];
    g_scale[ch] = sc;
    g_shift[ch] = beta[ch] - mean*sc;
}

// ---------------------------------------------------------------------------
// Kernel D: normalize + ReLU -> d_out
// ---------------------------------------------------------------------------
__global__ __launch_bounds__(256)
void norm_kernel(float4* __restrict__ out) {
    const int i0 = blockIdx.x * 256 + threadIdx.x;
    const int HALF = (NPIX*CHO/4)/2;
    #pragma unroll
    for (int k = 0; k < 2; k++) {
        const int i = i0 + k*HALF;
        const int c = (i >> 12) & 63;
        const float sc = g_scale[c];
        const float sh = g_shift[c];
        float4 v = ((const float4*)g_y)[i];
        v.x = fmaxf(v.x*sc + sh, 0.f);
        v.y = fmaxf(v.y*sc + sh, 0.f);
        v.z = fmaxf(v.z*sc + sh, 0.f);
        v.w = fmaxf(v.w*sc + sh, 0.f);
        out[i] = v;
    }
}

extern "C" void kernel_launch(void* const* d_in, const int* in_sizes, int n_in,
                              void* d_out, int out_size) {
    const float* x     = (const float*)d_in[0];
    const float* w_off = (const float*)d_in[1];
    const float* b_off = (const float*)d_in[2];
    const float* w     = (const float*)d_in[3];
    const float* b     = (const float*)d_in[4];
    const float* gamma = (const float*)d_in[5];
    const float* beta  = (const float*)d_in[6];

    cudaFuncSetAttribute(offset_conv_kernel,
                         cudaFuncAttributeMaxDynamicSharedMemorySize, 9*64*28*4);
    cudaFuncSetAttribute(deform_mma_kernel,
                         cudaFuncAttributeMaxDynamicSharedMemorySize, DSMEM);

    offset_conv_kernel<<<NPIX/512, 512, 9*64*28*4>>>(x, w_off, b_off);
    deform_mma_kernel<<<NPIX/256, 256, DSMEM>>>(x, w, b);
    stats1_kernel<<<64*8, 256>>>();
    stats2_kernel<<<1, 64>>>(gamma, beta);
    norm_kernel<<<(NPIX*CHO/4/2)/256, 256>>>((float4*)d_out);
}

// round 14
// speedup vs baseline: 2.4458x; 1.2392x over previous
#include <cuda_runtime.h>
#include <math.h>
#include <stdint.h>

#define CHI 64
#define CHO 64
#define HH 128
#define WW 128
#define BB 4
#define HW (HH*WW)          /* 16384 pixels per plane */
#define NPIX (BB*HW)        /* 65536 pixels total */

// Scratch buffers (static device globals; no allocation anywhere)
__device__ float g_off[BB*27*HW];     // offset-conv output, 27 channels
__device__ float g_y[BB*CHO*HW];      // pre-BN deform-conv output
__device__ float g_part[64*8*2];      // BN stage-1 partial sums
__device__ float g_scale[CHO];
__device__ float g_shift[CHO];

// ======== tf32 mma.sync primitives (sm_80+ PTX; valid at target sm_103) =====
__device__ __forceinline__ uint32_t f2tf32(float v) {
    uint32_t r;
    asm("cvt.rna.tf32.f32 %0, %1;" : "=r"(r) : "f"(v));
    return r;
}
__device__ __forceinline__ void mma_tf32(float* d, const uint32_t* a,
                                         const uint32_t* b) {
    asm volatile(
        "mma.sync.aligned.m16n8k8.row.col.f32.tf32.tf32.f32 "
        "{%0,%1,%2,%3}, {%4,%5,%6,%7}, {%8,%9}, {%0,%1,%2,%3};"
        : "+f"(d[0]), "+f"(d[1]), "+f"(d[2]), "+f"(d[3])
        : "r"(a[0]), "r"(a[1]), "r"(a[2]), "r"(a[3]), "r"(b[0]), "r"(b[1]));
}

// ======== deform tap: folds bilinear weights, validity, sigmoid mask ========
struct Tap {
    float w00, w01, w10, w11;
    int   i00, i01, i10, i11;
};

__device__ __forceinline__ Tap make_tap(const float* offb, int kk, int h, int wx) {
    Tap t;
    const float dy = offb[(2*kk  )*HW];
    const float dx = offb[(2*kk+1)*HW];
    const float ml = offb[(18+kk)*HW];
    const float mask = 1.f / (1.f + __expf(-ml));
    const int ky = kk / 3;
    const int kx = kk - ky*3;
    const float py = (float)(h  - 1 + ky) + dy;
    const float px = (float)(wx - 1 + kx) + dx;
    const float fy0 = floorf(py);
    const float fx0 = floorf(px);
    const float wy  = py - fy0;
    const float wxf = px - fx0;
    const int iy0 = (int)fy0;
    const int ix0 = (int)fx0;
    const int iy1 = iy0 + 1;
    const int ix1 = ix0 + 1;
    const float vy0 = (iy0 >= 0 && iy0 < HH) ? 1.f : 0.f;
    const float vy1 = (iy1 >= 0 && iy1 < HH) ? 1.f : 0.f;
    const float vx0 = (ix0 >= 0 && ix0 < WW) ? 1.f : 0.f;
    const float vx1 = (ix1 >= 0 && ix1 < WW) ? 1.f : 0.f;
    const int cy0 = min(max(iy0, 0), HH-1);
    const int cy1 = min(max(iy1, 0), HH-1);
    const int cx0 = min(max(ix0, 0), WW-1);
    const int cx1 = min(max(ix1, 0), WW-1);
    t.w00 = (1.f-wy)*(1.f-wxf)*vy0*vx0*mask;
    t.w01 = (1.f-wy)*wxf      *vy0*vx1*mask;
    t.w10 = wy      *(1.f-wxf)*vy1*vx0*mask;
    t.w11 = wy      *wxf      *vy1*vx1*mask;
    t.i00 = cy0*WW + cx0;
    t.i01 = cy0*WW + cx1;
    t.i10 = cy1*WW + cx0;
    t.i11 = cy1*WW + cx1;
    return t;
}

// ===========================================================================
// Kernel A: offset conv (64 -> 27 ch, 3x3, pad 1) via tf32 mma.sync.
// Grid NPIX/256, block 256, 2 CTAs/SM. Per CTA: M=256 pixels, N=32 (27
// used, rest zero-padded), K=9 taps x 64 channels. Warp tile 32 px x 32 out.
// Gather is ONE predicated coalesced load per (channel, pixel).
// ===========================================================================
#define OVPAD 264
#define OWPAD 68
#define OW_OFF (64*OVPAD)
#define OSMEM ((64*OVPAD + 32*OWPAD) * 4)   /* 76288 bytes */

__global__ __launch_bounds__(256, 2)
void offset_mma_kernel(const float* __restrict__ x,
                       const float* __restrict__ w_off,
                       const float* __restrict__ b_off) {
    extern __shared__ uint32_t sm[];
    uint32_t* Vt = sm;            // value tile,  [64][OVPAD]
    uint32_t* Ws = sm + OW_OFF;   // weight tile, [32][OWPAD]

    const int tid  = threadIdx.x;
    const int warp = tid >> 5;
    const int lane = tid & 31;
    const int gr   = lane >> 2;
    const int gc   = lane & 3;
    const int m0   = warp << 5;

    const int blk     = blockIdx.x;
    const int b       = blk >> 6;
    const int remBase = (blk & 63) << 8;
    const int rem     = remBase + tid;
    const int h       = rem >> 7;
    const int wx      = rem & 127;
    const float* xb   = x + b*(CHI*HW);

    float acc[2][4][4];
    #pragma unroll
    for (int mt = 0; mt < 2; mt++)
        #pragma unroll
        for (int n = 0; n < 4; n++)
            #pragma unroll
            for (int q = 0; q < 4; q++)
                acc[mt][n][q] = 0.f;

    for (int kk = 0; kk < 9; kk++) {
        const int ky = kk / 3;
        const int kx = kk - ky*3;

        // stage W chunk kk: 32 x 64 (rows 27..31 zeroed)
        #pragma unroll
        for (int j = 0; j < 8; j++) {
            const int i = tid + (j << 8);
            const int o = i >> 6;
            const int c = i & 63;
            Ws[o*OWPAD + c] = (o < 27) ? f2tf32(w_off[o*576 + c*9 + kk]) : 0u;
        }
        // gather this thread's pixel across all channels
        {
            const int yy = h + ky - 1;
            const int xx = wx + kx - 1;
            const bool ok = (yy >= 0 && yy < HH && xx >= 0 && xx < WW);
            const float* xp = xb + (ok ? yy*WW + xx : 0);
            #pragma unroll 8
            for (int c = 0; c < 64; c++)
                Vt[c*OVPAD + tid] = f2tf32(ok ? xp[c*HW] : 0.f);
        }
        __syncthreads();

        #pragma unroll
        for (int kc = 0; kc < 8; kc++) {
            const int k0 = kc << 3;
            uint32_t bf[4][2];
            #pragma unroll
            for (int n = 0; n < 4; n++) {
                const int orow = (n << 3) + gr;
                bf[n][0] = Ws[orow*OWPAD + k0 + gc];
                bf[n][1] = Ws[orow*OWPAD + k0 + gc + 4];
            }
            uint32_t af[2][4];
            #pragma unroll
            for (int mt = 0; mt < 2; mt++) {
                const int m = m0 + (mt << 4);
                af[mt][0] = Vt[(k0 + gc    )*OVPAD + m + gr];
                af[mt][1] = Vt[(k0 + gc    )*OVPAD + m + gr + 8];
                af[mt][2] = Vt[(k0 + gc + 4)*OVPAD + m + gr];
                af[mt][3] = Vt[(k0 + gc + 4)*OVPAD + m + gr + 8];
            }
            #pragma unroll
            for (int mt = 0; mt < 2; mt++)
                #pragma unroll
                for (int n = 0; n < 4; n++)
                    mma_tf32(acc[mt][n], af[mt], bf[n]);
        }
        __syncthreads();
    }

    // write the 27 live channels (+ bias)
    float* ob = g_off + b*(27*HW);
    const int o0 = gc << 1;
    #pragma unroll
    for (int mt = 0; mt < 2; mt++) {
        const int r0 = remBase + m0 + (mt << 4) + gr;
        #pragma unroll
        for (int n = 0; n < 4; n++) {
            const int oa = (n << 3) + o0;
            if (oa < 27) {
                const float bv = b_off[oa];
                ob[oa*HW + r0    ] = acc[mt][n][0] + bv;
                ob[oa*HW + r0 + 8] = acc[mt][n][2] + bv;
            }
            if (oa + 1 < 27) {
                const float bv = b_off[oa+1];
                ob[(oa+1)*HW + r0    ] = acc[mt][n][1] + bv;
                ob[(oa+1)*HW + r0 + 8] = acc[mt][n][3] + bv;
            }
        }
    }
}

// ===========================================================================
// Kernel B: deformable gather + tf32 mma.sync contraction (passed R10).
// Grid NPIX/256, block 256, 2 CTAs/SM. Warp tile 32 px x 64 outputs.
// ===========================================================================
#define VPAD 264
#define WPAD 68
#define W_OFF (64*VPAD)
#define DSMEM ((64*VPAD + 64*WPAD) * 4)   /* 84992 bytes */

__global__ __launch_bounds__(256, 2)
void deform_mma_kernel(const float* __restrict__ x,
                       const float* __restrict__ w,
                       const float* __restrict__ bias) {
    extern __shared__ uint32_t sm[];
    uint32_t* Vt = sm;           // [64][VPAD]
    uint32_t* Ws = sm + W_OFF;   // [64][WPAD]

    const int tid  = threadIdx.x;
    const int warp = tid >> 5;
    const int lane = tid & 31;
    const int gr   = lane >> 2;
    const int gc   = lane & 3;
    const int m0   = warp << 5;

    const int p    = blockIdx.x * 256 + tid;
    const int b    = p >> 14;
    const int rem  = p & 16383;
    const int h    = rem >> 7;
    const int wx   = rem & 127;
    const int remBase = (int)(blockIdx.x & 63) << 8;

    const float* xb   = x + b*(CHI*HW);
    const float* offb = g_off + b*(27*HW) + rem;

    float acc[2][8][4];
    #pragma unroll
    for (int mt = 0; mt < 2; mt++)
        #pragma unroll
        for (int n = 0; n < 8; n++)
            #pragma unroll
            for (int q = 0; q < 4; q++)
                acc[mt][n][q] = 0.f;

    for (int kk = 0; kk < 9; kk++) {
        // stage W chunk kk: 64 x 64
        #pragma unroll
        for (int j = 0; j < 16; j++) {
            const int i = tid + (j << 8);
            const int o = i >> 6;
            const int c = i & 63;
            Ws[o*WPAD + c] = f2tf32(w[o*576 + c*9 + kk]);
        }
        // bilinear gather for this thread's pixel across all channels
        {
            const Tap tp = make_tap(offb, kk, h, wx);
            const float* p00 = xb + tp.i00;
            const float* p01 = xb + tp.i01;
            const float* p10 = xb + tp.i10;
            const float* p11 = xb + tp.i11;
            #pragma unroll 8
            for (int c = 0; c < 64; c++) {
                const int off = c*HW;
                const float v = tp.w00*p00[off] + tp.w01*p01[off]
                              + tp.w10*p10[off] + tp.w11*p11[off];
                Vt[c*VPAD + tid] = f2tf32(v);
            }
        }
        __syncthreads();

        #pragma unroll
        for (int kc = 0; kc < 8; kc++) {
            const int k0 = kc << 3;
            uint32_t bf[8][2];
            #pragma unroll
            for (int n = 0; n < 8; n++) {
                const int orow = (n << 3) + gr;
                bf[n][0] = Ws[orow*WPAD + k0 + gc];
                bf[n][1] = Ws[orow*WPAD + k0 + gc + 4];
            }
            uint32_t af[2][4];
            #pragma unroll
            for (int mt = 0; mt < 2; mt++) {
                const int m = m0 + (mt << 4);
                af[mt][0] = Vt[(k0 + gc    )*VPAD + m + gr];
                af[mt][1] = Vt[(k0 + gc    )*VPAD + m + gr + 8];
                af[mt][2] = Vt[(k0 + gc + 4)*VPAD + m + gr];
                af[mt][3] = Vt[(k0 + gc + 4)*VPAD + m + gr + 8];
            }
            #pragma unroll
            for (int mt = 0; mt < 2; mt++)
                #pragma unroll
                for (int n = 0; n < 8; n++)
                    mma_tf32(acc[mt][n], af[mt], bf[n]);
        }
        __syncthreads();
    }

    float* yb = g_y + b*(CHO*HW);
    const int o0 = gc << 1;
    #pragma unroll
    for (int mt = 0; mt < 2; mt++) {
        const int r0 = remBase + m0 + (mt << 4) + gr;
        #pragma unroll
        for (int n = 0; n < 8; n++) {
            const int oa = (n << 3) + o0;
            const float b0 = bias[oa];
            const float b1 = bias[oa+1];
            yb[ oa   *HW + r0    ] = acc[mt][n][0] + b0;
            yb[(oa+1)*HW + r0    ] = acc[mt][n][1] + b1;
            yb[ oa   *HW + r0 + 8] = acc[mt][n][2] + b0;
            yb[(oa+1)*HW + r0 + 8] = acc[mt][n][3] + b1;
        }
    }
}

// ===========================================================================
// Kernel C1: BN stats stage 1 (deterministic per-block tree reduction)
// ===========================================================================
__global__ __launch_bounds__(256)
void stats1_kernel() {
    const int ch    = blockIdx.x >> 3;
    const int slice = blockIdx.x & 7;
    const int b     = slice >> 1;
    const int q0    = (slice & 1) * 8192;
    const int tid   = threadIdx.x;
    const float4* src = (const float4*)(g_y + b*(CHO*HW) + ch*HW + q0);
    float s = 0.f, ss = 0.f;
    #pragma unroll
    for (int it = 0; it < 8; it++) {
        float4 v = src[it*256 + tid];
        s  += v.x + v.y + v.z + v.w;
        ss += v.x*v.x + v.y*v.y + v.z*v.z + v.w*v.w;
    }
    __shared__ float sh_s[256], sh_ss[256];
    sh_s[tid] = s;
    sh_ss[tid] = ss;
    __syncthreads();
    for (int st = 128; st > 0; st >>= 1) {
        if (tid < st) { sh_s[tid] += sh_s[tid+st]; sh_ss[tid] += sh_ss[tid+st]; }
        __syncthreads();
    }
    if (tid == 0) {
        g_part[(ch*8 + slice)*2 + 0] = sh_s[0];
        g_part[(ch*8 + slice)*2 + 1] = sh_ss[0];
    }
}

// ===========================================================================
// Kernel C2: finalize per-channel scale/shift
// ===========================================================================
__global__ void stats2_kernel(const float* __restrict__ gamma,
                              const float* __restrict__ beta) {
    const int ch = threadIdx.x;
    if (ch >= 64) return;
    float s = 0.f, ss = 0.f;
    #pragma unroll
    for (int j = 0; j < 8; j++) {
        s  += g_part[(ch*8 + j)*2 + 0];
        ss += g_part[(ch*8 + j)*2 + 1];
    }
    const float inv  = 1.f / (float)NPIX;
    const float mean = s * inv;
    const float var  = ss * inv - mean*mean;
    const float rstd = rsqrtf(var + 1e-5f);
    const float sc   = rstd * gamma[ch];
    g_scale[ch] = sc;
    g_shift[ch] = beta[ch] - mean*sc;
}

// ===========================================================================
// Kernel D: normalize + ReLU -> d_out (two float4 per thread)
// ===========================================================================
__global__ __launch_bounds__(256)
void norm_kernel(float4* __restrict__ out) {
    const int i0   = blockIdx.x * 256 + threadIdx.x;
    const int HALF = (NPIX*CHO/4) / 2;
    #pragma unroll
    for (int k = 0; k < 2; k++) {
        const int i = i0 + k*HALF;
        const int c = (i >> 12) & 63;
        const float sc = g_scale[c];
        const float sh = g_shift[c];
        float4 v = ((const float4*)g_y)[i];
        v.x = fmaxf(v.x*sc + sh, 0.f);
        v.y = fmaxf(v.y*sc + sh, 0.f);
        v.z = fmaxf(v.z*sc + sh, 0.f);
        v.w = fmaxf(v.w*sc + sh, 0.f);
        out[i] = v;
    }
}

extern "C" void kernel_launch(void* const* d_in, const int* in_sizes, int n_in,
                              void* d_out, int out_size) {
    const float* x     = (const float*)d_in[0];
    const float* w_off = (const float*)d_in[1];
    const float* b_off = (const float*)d_in[2];
    const float* w     = (const float*)d_in[3];
    const float* b     = (const float*)d_in[4];
    const float* gamma = (const float*)d_in[5];
    const float* beta  = (const float*)d_in[6];

    cudaFuncSetAttribute(offset_mma_kernel,
                         cudaFuncAttributeMaxDynamicSharedMemorySize, OSMEM);
    cudaFuncSetAttribute(deform_mma_kernel,
                         cudaFuncAttributeMaxDynamicSharedMemorySize, DSMEM);

    offset_mma_kernel<<<NPIX/256, 256, OSMEM>>>(x, w_off, b_off);
    deform_mma_kernel<<<NPIX/256, 256, DSMEM>>>(x, w, b);
    stats1_kernel<<<64*8, 256>>>();
    stats2_kernel<<<1, 64>>>(gamma, beta);
    norm_kernel<<<(NPIX*CHO/4/2)/256, 256>>>((float4*)d_out);
}

// round 15
// speedup vs baseline: 2.7271x; 1.1150x over previous
#include <cuda_runtime.h>
#include <math.h>
#include <stdint.h>

#define CHI 64
#define CHO 64
#define HH 128
#define WW 128
#define BB 4
#define HW (HH*WW)          /* 16384 pixels per plane */
#define NPIX (BB*HW)        /* 65536 pixels total */

// Scratch buffers (static device globals; no allocation anywhere)
__device__ float g_off[BB*27*HW];     // offset-conv output, 27 channels
__device__ float g_y[BB*CHO*HW];      // pre-BN deform-conv output
__device__ float g_part[64*256*2];    // BN partials: [ch][cta] sums, then squares
__device__ float g_scale[CHO];
__device__ float g_shift[CHO];

// ======== tf32 mma.sync primitives (sm_80+ PTX; valid at target sm_103) =====
__device__ __forceinline__ uint32_t f2tf32(float v) {
    uint32_t r;
    asm("cvt.rna.tf32.f32 %0, %1;" : "=r"(r) : "f"(v));
    return r;
}
__device__ __forceinline__ void mma_tf32(float* d, const uint32_t* a,
                                         const uint32_t* b) {
    asm volatile(
        "mma.sync.aligned.m16n8k8.row.col.f32.tf32.tf32.f32 "
        "{%0,%1,%2,%3}, {%4,%5,%6,%7}, {%8,%9}, {%0,%1,%2,%3};"
        : "+f"(d[0]), "+f"(d[1]), "+f"(d[2]), "+f"(d[3])
        : "r"(a[0]), "r"(a[1]), "r"(a[2]), "r"(a[3]), "r"(b[0]), "r"(b[1]));
}

// ======== deform tap: folds bilinear weights, validity, sigmoid mask ========
struct Tap {
    float w00, w01, w10, w11;
    int   i00, i01, i10, i11;
};

__device__ __forceinline__ Tap make_tap(const float* offb, int kk, int h, int wx) {
    Tap t;
    const float dy = offb[(2*kk  )*HW];
    const float dx = offb[(2*kk+1)*HW];
    const float ml = offb[(18+kk)*HW];
    const float mask = 1.f / (1.f + __expf(-ml));
    const int ky = kk / 3;
    const int kx = kk - ky*3;
    const float py = (float)(h  - 1 + ky) + dy;
    const float px = (float)(wx - 1 + kx) + dx;
    const float fy0 = floorf(py);
    const float fx0 = floorf(px);
    const float wy  = py - fy0;
    const float wxf = px - fx0;
    const int iy0 = (int)fy0;
    const int ix0 = (int)fx0;
    const int iy1 = iy0 + 1;
    const int ix1 = ix0 + 1;
    const float vy0 = (iy0 >= 0 && iy0 < HH) ? 1.f : 0.f;
    const float vy1 = (iy1 >= 0 && iy1 < HH) ? 1.f : 0.f;
    const float vx0 = (ix0 >= 0 && ix0 < WW) ? 1.f : 0.f;
    const float vx1 = (ix1 >= 0 && ix1 < WW) ? 1.f : 0.f;
    const int cy0 = min(max(iy0, 0), HH-1);
    const int cy1 = min(max(iy1, 0), HH-1);
    const int cx0 = min(max(ix0, 0), WW-1);
    const int cx1 = min(max(ix1, 0), WW-1);
    t.w00 = (1.f-wy)*(1.f-wxf)*vy0*vx0*mask;
    t.w01 = (1.f-wy)*wxf      *vy0*vx1*mask;
    t.w10 = wy      *(1.f-wxf)*vy1*vx0*mask;
    t.w11 = wy      *wxf      *vy1*vx1*mask;
    t.i00 = cy0*WW + cx0;
    t.i01 = cy0*WW + cx1;
    t.i10 = cy1*WW + cx0;
    t.i11 = cy1*WW + cx1;
    return t;
}

// ===========================================================================
// Kernel A: offset conv (64 -> 27 ch, 3x3, pad 1) via tf32 mma.sync.
// ===========================================================================
#define OVPAD 264
#define OWPAD 68
#define OW_OFF (64*OVPAD)
#define OSMEM ((64*OVPAD + 32*OWPAD) * 4)   /* 76288 bytes */

__global__ __launch_bounds__(256, 2)
void offset_mma_kernel(const float* __restrict__ x,
                       const float* __restrict__ w_off,
                       const float* __restrict__ b_off) {
    extern __shared__ uint32_t sm[];
    uint32_t* Vt = sm;            // [64][OVPAD]
    uint32_t* Ws = sm + OW_OFF;   // [32][OWPAD]

    const int tid  = threadIdx.x;
    const int warp = tid >> 5;
    const int lane = tid & 31;
    const int gr   = lane >> 2;
    const int gc   = lane & 3;
    const int m0   = warp << 5;

    const int blk     = blockIdx.x;
    const int b       = blk >> 6;
    const int remBase = (blk & 63) << 8;
    const int rem     = remBase + tid;
    const int h       = rem >> 7;
    const int wx      = rem & 127;
    const float* xb   = x + b*(CHI*HW);

    float acc[2][4][4];
    #pragma unroll
    for (int mt = 0; mt < 2; mt++)
        #pragma unroll
        for (int n = 0; n < 4; n++)
            #pragma unroll
            for (int q = 0; q < 4; q++)
                acc[mt][n][q] = 0.f;

    for (int kk = 0; kk < 9; kk++) {
        const int ky = kk / 3;
        const int kx = kk - ky*3;

        #pragma unroll
        for (int j = 0; j < 8; j++) {
            const int i = tid + (j << 8);
            const int o = i >> 6;
            const int c = i & 63;
            Ws[o*OWPAD + c] = (o < 27) ? f2tf32(w_off[o*576 + c*9 + kk]) : 0u;
        }
        {
            const int yy = h + ky - 1;
            const int xx = wx + kx - 1;
            const bool ok = (yy >= 0 && yy < HH && xx >= 0 && xx < WW);
            const float* xp = xb + (ok ? yy*WW + xx : 0);
            #pragma unroll 8
            for (int c = 0; c < 64; c++)
                Vt[c*OVPAD + tid] = f2tf32(ok ? xp[c*HW] : 0.f);
        }
        __syncthreads();

        #pragma unroll
        for (int kc = 0; kc < 8; kc++) {
            const int k0 = kc << 3;
            uint32_t bf[4][2];
            #pragma unroll
            for (int n = 0; n < 4; n++) {
                const int orow = (n << 3) + gr;
                bf[n][0] = Ws[orow*OWPAD + k0 + gc];
                bf[n][1] = Ws[orow*OWPAD + k0 + gc + 4];
            }
            uint32_t af[2][4];
            #pragma unroll
            for (int mt = 0; mt < 2; mt++) {
                const int m = m0 + (mt << 4);
                af[mt][0] = Vt[(k0 + gc    )*OVPAD + m + gr];
                af[mt][1] = Vt[(k0 + gc    )*OVPAD + m + gr + 8];
                af[mt][2] = Vt[(k0 + gc + 4)*OVPAD + m + gr];
                af[mt][3] = Vt[(k0 + gc + 4)*OVPAD + m + gr + 8];
            }
            #pragma unroll
            for (int mt = 0; mt < 2; mt++)
                #pragma unroll
                for (int n = 0; n < 4; n++)
                    mma_tf32(acc[mt][n], af[mt], bf[n]);
        }
        __syncthreads();
    }

    float* ob = g_off + b*(27*HW);
    const int o0 = gc << 1;
    #pragma unroll
    for (int mt = 0; mt < 2; mt++) {
        const int r0 = remBase + m0 + (mt << 4) + gr;
        #pragma unroll
        for (int n = 0; n < 4; n++) {
            const int oa = (n << 3) + o0;
            if (oa < 27) {
                const float bv = b_off[oa];
                ob[oa*HW + r0    ] = acc[mt][n][0] + bv;
                ob[oa*HW + r0 + 8] = acc[mt][n][2] + bv;
            }
            if (oa + 1 < 27) {
                const float bv = b_off[oa+1];
                ob[(oa+1)*HW + r0    ] = acc[mt][n][1] + bv;
                ob[(oa+1)*HW + r0 + 8] = acc[mt][n][3] + bv;
            }
        }
    }
}

// ===========================================================================
// Kernel B: deformable gather + tf32 mma.sync contraction, with BN stage-1
// partials fused into the epilogue (per-CTA per-channel sum / sumsq).
// ===========================================================================
#define VPAD 264
#define WPAD 68
#define W_OFF (64*VPAD)
#define DSMEM ((64*VPAD + 64*WPAD) * 4)   /* 84992 bytes */

__global__ __launch_bounds__(256, 2)
void deform_mma_kernel(const float* __restrict__ x,
                       const float* __restrict__ w,
                       const float* __restrict__ bias) {
    extern __shared__ uint32_t sm[];
    uint32_t* Vt = sm;           // [64][VPAD]
    uint32_t* Ws = sm + W_OFF;   // [64][WPAD]

    const int tid  = threadIdx.x;
    const int warp = tid >> 5;
    const int lane = tid & 31;
    const int gr   = lane >> 2;
    const int gc   = lane & 3;
    const int m0   = warp << 5;

    const int p    = blockIdx.x * 256 + tid;
    const int b    = p >> 14;
    const int rem  = p & 16383;
    const int h    = rem >> 7;
    const int wx   = rem & 127;
    const int remBase = (int)(blockIdx.x & 63) << 8;

    const float* xb   = x + b*(CHI*HW);
    const float* offb = g_off + b*(27*HW) + rem;

    float acc[2][8][4];
    #pragma unroll
    for (int mt = 0; mt < 2; mt++)
        #pragma unroll
        for (int n = 0; n < 8; n++)
            #pragma unroll
            for (int q = 0; q < 4; q++)
                acc[mt][n][q] = 0.f;

    for (int kk = 0; kk < 9; kk++) {
        #pragma unroll
        for (int j = 0; j < 16; j++) {
            const int i = tid + (j << 8);
            const int o = i >> 6;
            const int c = i & 63;
            Ws[o*WPAD + c] = f2tf32(w[o*576 + c*9 + kk]);
        }
        {
            const Tap tp = make_tap(offb, kk, h, wx);
            const float* p00 = xb + tp.i00;
            const float* p01 = xb + tp.i01;
            const float* p10 = xb + tp.i10;
            const float* p11 = xb + tp.i11;
            #pragma unroll 8
            for (int c = 0; c < 64; c++) {
                const int off = c*HW;
                const float v = tp.w00*p00[off] + tp.w01*p01[off]
                              + tp.w10*p10[off] + tp.w11*p11[off];
                Vt[c*VPAD + tid] = f2tf32(v);
            }
        }
        __syncthreads();

        #pragma unroll
        for (int kc = 0; kc < 8; kc++) {
            const int k0 = kc << 3;
            uint32_t bf[8][2];
            #pragma unroll
            for (int n = 0; n < 8; n++) {
                const int orow = (n << 3) + gr;
                bf[n][0] = Ws[orow*WPAD + k0 + gc];
                bf[n][1] = Ws[orow*WPAD + k0 + gc + 4];
            }
            uint32_t af[2][4];
            #pragma unroll
            for (int mt = 0; mt < 2; mt++) {
                const int m = m0 + (mt << 4);
                af[mt][0] = Vt[(k0 + gc    )*VPAD + m + gr];
                af[mt][1] = Vt[(k0 + gc    )*VPAD + m + gr + 8];
                af[mt][2] = Vt[(k0 + gc + 4)*VPAD + m + gr];
                af[mt][3] = Vt[(k0 + gc + 4)*VPAD + m + gr + 8];
            }
            #pragma unroll
            for (int mt = 0; mt < 2; mt++)
                #pragma unroll
                for (int n = 0; n < 8; n++)
                    mma_tf32(acc[mt][n], af[mt], bf[n]);
        }
        __syncthreads();   // last iteration: barrier before SMEM reuse below
    }

    // Epilogue: y = acc + bias -> g_y, and per-CTA BN partials.
    // Thread (gr, gc) holds channels oa = 8n+2gc (+1), pixels r0A, r0A+8,
    // r0B, r0B+8. Warp-sum over gr via 3 deterministic xor-shuffles; lane
    // gr==0 writes per-warp table in reused SMEM; threads 0..63 finalize.
    float* yb    = g_y + b*(CHO*HW);
    float* ws_s  = (float*)sm;         // [8][64]
    float* ws_ss = (float*)sm + 512;   // [8][64]
    const int o0  = gc << 1;
    const int r0A = remBase + m0 + gr;
    const int r0B = r0A + 16;
    #pragma unroll
    for (int n = 0; n < 8; n++) {
        const int oa = (n << 3) + o0;
        const float b0 = bias[oa];
        const float b1 = bias[oa+1];
        const float y00 = acc[0][n][0] + b0;
        const float y01 = acc[0][n][1] + b1;
        const float y02 = acc[0][n][2] + b0;
        const float y03 = acc[0][n][3] + b1;
        const float y10 = acc[1][n][0] + b0;
        const float y11 = acc[1][n][1] + b1;
        const float y12 = acc[1][n][2] + b0;
        const float y13 = acc[1][n][3] + b1;
        yb[ oa   *HW + r0A    ] = y00;
        yb[(oa+1)*HW + r0A    ] = y01;
        yb[ oa   *HW + r0A + 8] = y02;
        yb[(oa+1)*HW + r0A + 8] = y03;
        yb[ oa   *HW + r0B    ] = y10;
        yb[(oa+1)*HW + r0B    ] = y11;
        yb[ oa   *HW + r0B + 8] = y12;
        yb[(oa+1)*HW + r0B + 8] = y13;

        float s0  = y00 + y02 + y10 + y12;
        float ss0 = y00*y00 + y02*y02 + y10*y10 + y12*y12;
        float s1  = y01 + y03 + y11 + y13;
        float ss1 = y01*y01 + y03*y03 + y11*y11 + y13*y13;
        s0  += __shfl_xor_sync(0xffffffffu, s0, 4);
        s0  += __shfl_xor_sync(0xffffffffu, s0, 8);
        s0  += __shfl_xor_sync(0xffffffffu, s0, 16);
        ss0 += __shfl_xor_sync(0xffffffffu, ss0, 4);
        ss0 += __shfl_xor_sync(0xffffffffu, ss0, 8);
        ss0 += __shfl_xor_sync(0xffffffffu, ss0, 16);
        s1  += __shfl_xor_sync(0xffffffffu, s1, 4);
        s1  += __shfl_xor_sync(0xffffffffu, s1, 8);
        s1  += __shfl_xor_sync(0xffffffffu, s1, 16);
        ss1 += __shfl_xor_sync(0xffffffffu, ss1, 4);
        ss1 += __shfl_xor_sync(0xffffffffu, ss1, 8);
        ss1 += __shfl_xor_sync(0xffffffffu, ss1, 16);
        if (lane < 4) {
            ws_s [warp*64 + oa    ] = s0;
            ws_s [warp*64 + oa + 1] = s1;
            ws_ss[warp*64 + oa    ] = ss0;
            ws_ss[warp*64 + oa + 1] = ss1;
        }
    }
    __syncthreads();
    if (tid < 64) {
        float s = 0.f, q = 0.f;
        #pragma unroll
        for (int wg = 0; wg < 8; wg++) {
            s += ws_s [wg*64 + tid];
            q += ws_ss[wg*64 + tid];
        }
        g_part[tid*256 + blockIdx.x]         = s;
        g_part[16384 + tid*256 + blockIdx.x] = q;
    }
}

// ===========================================================================
// Kernel C: finalize per-channel scale/shift (64 blocks, one per channel)
// ===========================================================================
__global__ __launch_bounds__(256)
void stats2_kernel(const float* __restrict__ gamma,
                   const float* __restrict__ beta) {
    const int ch  = blockIdx.x;
    const int tid = threadIdx.x;
    __shared__ float sh_s[256], sh_ss[256];
    sh_s[tid]  = g_part[ch*256 + tid];
    sh_ss[tid] = g_part[16384 + ch*256 + tid];
    __syncthreads();
    for (int st = 128; st > 0; st >>= 1) {
        if (tid < st) { sh_s[tid] += sh_s[tid+st]; sh_ss[tid] += sh_ss[tid+st]; }
        __syncthreads();
    }
    if (tid == 0) {
        const float inv  = 1.f / (float)NPIX;
        const float mean = sh_s[0] * inv;
        const float var  = sh_ss[0] * inv - mean*mean;
        const float rstd = rsqrtf(var + 1e-5f);
        const float sc   = rstd * gamma[ch];
        g_scale[ch] = sc;
        g_shift[ch] = beta[ch] - mean*sc;
    }
}

// ===========================================================================
// Kernel D: normalize + ReLU -> d_out (four float4 per thread)
// ===========================================================================
__global__ __launch_bounds__(256)
void norm_kernel(float4* __restrict__ out) {
    const int i0 = blockIdx.x * 256 + threadIdx.x;
    const int QTR = (NPIX*CHO/4) / 4;
    #pragma unroll
    for (int k = 0; k < 4; k++) {
        const int i = i0 + k*QTR;
        const int c = (i >> 12) & 63;
        const float sc = g_scale[c];
        const float sh = g_shift[c];
        float4 v = ((const float4*)g_y)[i];
        v.x = fmaxf(v.x*sc + sh, 0.f);
        v.y = fmaxf(v.y*sc + sh, 0.f);
        v.z = fmaxf(v.z*sc + sh, 0.f);
        v.w = fmaxf(v.w*sc + sh, 0.f);
        out[i] = v;
    }
}

extern "C" void kernel_launch(void* const* d_in, const int* in_sizes, int n_in,
                              void* d_out, int out_size) {
    const float* x     = (const float*)d_in[0];
    const float* w_off = (const float*)d_in[1];
    const float* b_off = (const float*)d_in[2];
    const float* w     = (const float*)d_in[3];
    const float* b     = (const float*)d_in[4];
    const float* gamma = (const float*)d_in[5];
    const float* beta  = (const float*)d_in[6];

    cudaFuncSetAttribute(offset_mma_kernel,
                         cudaFuncAttributeMaxDynamicSharedMemorySize, OSMEM);
    cudaFuncSetAttribute(deform_mma_kernel,
                         cudaFuncAttributeMaxDynamicSharedMemorySize, DSMEM);

    offset_mma_kernel<<<NPIX/256, 256, OSMEM>>>(x, w_off, b_off);
    deform_mma_kernel<<<NPIX/256, 256, DSMEM>>>(x, w, b);
    stats2_kernel<<<64, 256>>>(gamma, beta);
    norm_kernel<<<(NPIX*CHO/4/4)/256, 256>>>((float4*)d_out);
}